// round 8
// baseline (speedup 1.0000x reference)
#include <cuda_runtime.h>
#include <cmath>
#include <cstdint>
#include <cstring>
#include <complex>
#include <vector>
#include <algorithm>

#define MAXE 7000
#define MAXG 600
#define MAXN 10000
#define NSLICE 8

static __device__ float g_Y0[(size_t)MAXN * 400];
static __device__ uint2 g_ent[MAXE];
static __device__ uint2 g_grp[MAXG];
__constant__ int c_sliceStart[NSLICE + 1];
__constant__ int c_dd0Start[NSLICE + 1];
__constant__ int c_dd1Start[NSLICE + 1];
__constant__ unsigned c_dd0Item[16];
__constant__ unsigned c_dd1Item[64];

typedef unsigned long long ull;

// f32x2 packed math (FFMA2/FMUL2 — PTX-only on sm_103a)
#define FMA2(d, a, b, c) asm("fma.rn.f32x2 %0, %1, %2, %3;" : "=l"(d) : "l"(a), "l"(b), "l"(c))
#define MUL2(d, a, b)    asm("mul.rn.f32x2 %0, %1, %2;"     : "=l"(d) : "l"(a), "l"(b))
#define SPLAT2(d, s)     asm("mov.b64 %0, {%1, %1};"        : "=l"(d) : "r"(s))

__device__ __forceinline__ ull ld2s(const float* p) { return *(const ull*)p; }
__device__ __forceinline__ ull ld2g(const float* p) { return __ldg((const ull*)p); }
__device__ __forceinline__ float2 unp(ull v) { float2 f; memcpy(&f, &v, 8); return f; }

// ------------------------- host tables -------------------------------------
namespace tab {
static int nent = 0, ngrp = 0;
static uint2 h_ent[MAXE];
static uint2 h_grp[MAXG];
static int h_sliceStart[NSLICE + 1];
static unsigned h_dd0Item[16], h_dd1Item[64];
static int h_dd0Start[NSLICE + 1], h_dd1Start[NSLICE + 1];
static bool built = false;

static double lf(int n) { return lgamma((double)n + 1.0); }

static double cgc(int l1, int m1, int l2, int m2, int l3, int m3) {
    if (m1 + m2 != m3 || l3 < abs(l1 - l2) || l3 > l1 + l2) return 0.0;
    double pre = 0.5 * (lf(l1+l2-l3) + lf(l1-l2+l3) + lf(-l1+l2+l3) - lf(l1+l2+l3+1)
                 + lf(l1+m1) + lf(l1-m1) + lf(l2+m2) + lf(l2-m2) + lf(l3+m3) + lf(l3-m3));
    int kmin = std::max(0, std::max(l2-l3-m1, l1-l3+m2));
    int kmax = std::min(l1+l2-l3, std::min(l1-m1, l2+m2));
    double s = 0.0;
    for (int k = kmin; k <= kmax; k++) {
        double ln = lf(k) + lf(l1+l2-l3-k) + lf(l1-m1-k) + lf(l2+m2-k)
                  + lf(l3-l2+m1+k) + lf(l3-l1-m2+k);
        s += ((k & 1) ? -1.0 : 1.0) * exp(pre - ln);
    }
    return sqrt(2.0*l3+1.0) * s;
}

static int degof(int lm){ return lm>=16?4: lm>=9?3: lm>=4?2: lm>=1?1:0; }

struct Rent { int path, ic, ia, ib; double v; };
static std::complex<double> Cc[25][25][25];

static void build() {
    if (built) return;
    built = true;
    int pid[5][5][5];
    for (int a=0;a<5;a++)for(int b=0;b<5;b++)for(int c=0;c<5;c++) pid[a][b][c]=-1;
    int np = 0;
    for (int l1=0;l1<=4;l1++)
        for (int l2=0;l2<=4;l2++)
            for (int l3=abs(l1-l2); l3<=std::min(4,l1+l2); l3++)
                pid[l1][l2][l3] = np++;

    for (int l1=0;l1<=4;l1++)
        for (int l2=0;l2<=4;l2++)
            for (int l3=abs(l1-l2); l3<=std::min(4,l1+l2); l3++)
                for (int m1=-l1;m1<=l1;m1++)
                    for (int m2=-l2;m2<=l2;m2++) {
                        int m3 = m1+m2;
                        if (abs(m3) <= l3)
                            Cc[l1*l1+l1+m1][l2*l2+l2+m2][l3*l3+l3+m3] = cgc(l1,m1,l2,m2,l3,m3);
                    }

    const double s2 = 1.0/sqrt(2.0);
    std::complex<double> Uv[25][2]; int Uc[25][2]; int Un[25];
    for (int l=0;l<=4;l++) {
        int off = l*l+l;
        Un[off]=1; Uc[off][0]=off; Uv[off][0]={1,0}; Uc[off][1]=off; Uv[off][1]={0,0};
        for (int m=1;m<=l;m++) {
            double sg = (m&1)?-1.0:1.0;
            Un[off+m]=2;
            Uc[off+m][0]=off+m; Uv[off+m][0]={sg*s2,0};
            Uc[off+m][1]=off-m; Uv[off+m][1]={s2,0};
            Un[off-m]=2;
            Uc[off-m][0]=off-m; Uv[off-m][0]={0,s2};
            Uc[off-m][1]=off+m; Uv[off-m][1]={0,-sg*s2};
        }
    }

    std::vector<Rent> es; es.reserve(5000);
    for (int i=0;i<25;i++)
        for (int j=0;j<25;j++)
            for (int k=0;k<25;k++) {
                std::complex<double> T(0,0);
                for (int a=0;a<Un[i];a++)
                    for (int b=0;b<Un[j];b++)
                        for (int c=0;c<Un[k];c++)
                            T += Uv[i][a]*Uv[j][b]*std::conj(Uv[c==c?k:k][0]*0.0+1.0)*0.0; // placeholder avoided
                (void)T;
                break;
            }
    es.clear();
    for (int i=0;i<25;i++)
        for (int j=0;j<25;j++)
            for (int k=0;k<25;k++) {
                std::complex<double> T(0,0);
                for (int a=0;a<Un[i];a++)
                    for (int b=0;b<Un[j];b++)
                        for (int c=0;c<Un[k];c++)
                            T += Uv[i][a]*Uv[j][b]*std::conj(Uv[k][c])*Cc[Uc[i][a]][Uc[j][b]][Uc[k][c]];
                double C = T.real() + T.imag();
                if (std::fabs(C) < 1e-12) continue;
                int p = pid[degof(i)][degof(j)][degof(k)];
                if (p < 0) continue;
                es.push_back({p, k, i, j, C});
            }

    std::sort(es.begin(), es.end(), [](const Rent&a, const Rent&b){
        if (a.path!=b.path) return a.path<b.path;
        if (a.ic!=b.ic) return a.ic<b.ic;
        if (a.ia!=b.ia) return a.ia<b.ia;
        return a.ib<b.ib; });

    nent = (int)std::min((size_t)MAXE, es.size());

    // groups on (path, ic) boundaries; entries get a "reload-a" flag (bit 15)
    std::vector<int> gstart, gcnt, gic, gss, gpath;
    int lastp=-1, lastic=-1, lastia=-1;
    for (int e=0;e<nent;e++) {
        bool newgrp = (es[e].path!=lastp || es[e].ic!=lastic);
        if (newgrp) {
            lastp = es[e].path; lastic = es[e].ic; lastia = -1;
            gstart.push_back(e); gcnt.push_back(0);
            gic.push_back(es[e].ic);
            gss.push_back((degof(es[e].ia)+degof(es[e].ib)+degof(es[e].ic))&1);
            gpath.push_back(es[e].path);
        }
        gcnt.back()++;
        unsigned iao = (unsigned)(es[e].ia*128);
        if (es[e].ia != lastia) { iao |= 0x8000u; lastia = es[e].ia; }
        h_ent[e].x = iao | ((unsigned)(es[e].ib*128)<<16);
        float vv = (float)es[e].v;
        unsigned vb; memcpy(&vb, &vv, 4);
        h_ent[e].y = vb;
    }
    int NG = (int)gstart.size();

    // greedy slice assignment over NSLICE warps
    {
        std::vector<int> ord(NG);
        for (int g=0; g<NG; g++) ord[g]=g;
        std::sort(ord.begin(), ord.end(), [&](int a, int b){ return gcnt[a]>gcnt[b]; });
        std::vector<int> sl(NG); long load[NSLICE]={0};
        for (int oi=0; oi<NG; oi++) {
            int g = ord[oi];
            int m=0;
            for (int k=1;k<NSLICE;k++) if (load[k]<load[m]) m=k;
            sl[g]=m; load[m]+=gcnt[g]+4;
        }
        int pos=0;
        for (int s=0;s<NSLICE;s++) {
            h_sliceStart[s]=pos;
            for (int g=0; g<NG && pos<MAXG; g++) if (sl[g]==s) {
                h_grp[pos].x = (unsigned)gstart[g] | ((unsigned)gcnt[g]<<16);
                h_grp[pos].y = (unsigned)gic[g] | ((unsigned)gss[g]<<5) | ((unsigned)gpath[g]<<8);
                pos++;
            }
        }
        h_sliceStart[NSLICE]=pos; ngrp=pos;
    }

    // dd work items: enc = f0 | fc<<8 | L<<16 | p<<19
    auto pack=[](int p,int L,int f0,int fc){
        return (unsigned)f0 | ((unsigned)fc<<8) | ((unsigned)L<<16) | ((unsigned)p<<19);
    };
    struct It { unsigned enc; int cost; };
    auto greedy=[&](std::vector<It>& v, unsigned* items, int* starts){
        std::sort(v.begin(), v.end(), [](const It&a, const It&b){ return a.cost>b.cost; });
        long load[NSLICE]={0};
        std::vector<int> asg(v.size());
        for (size_t i=0;i<v.size();i++) {
            int m=0;
            for (int k=1;k<NSLICE;k++) if (load[k]<load[m]) m=k;
            asg[i]=m; load[m]+=v[i].cost;
        }
        int pos=0;
        for (int s=0;s<NSLICE;s++) {
            starts[s]=pos;
            for (size_t i=0;i<v.size();i++) if (asg[i]==s) items[pos++]=v[i].enc;
        }
        starts[NSLICE]=pos;
    };
    {
        std::vector<It> v1;
        for (int p=0;p<2;p++)
            for (int L=0;L<5;L++) {
                int cost=(2*L+1)*64*2;
                int nch = (cost + 799)/800; if (nch<1) nch=1;
                int per = (64 + nch - 1)/nch; per = (per+1)&~1;
                for (int f0=0; f0<64; f0+=per) {
                    int fc = std::min(per, 64-f0);
                    v1.push_back({pack(p,L,f0,fc), (2*L+1)*fc*2});
                }
            }
        greedy(v1, h_dd1Item, h_dd1Start);
        std::vector<It> v0;
        for (int L=0;L<5;L++)
            v0.push_back({pack(0,L,0,16), (2*L+1)*16*2});
        greedy(v0, h_dd0Item, h_dd0Start);
    }
}
} // namespace tab

// ------------------------- edge kernel --------------------------------------
__global__ __launch_bounds__(256) void edge_kernel(
    const int* __restrict__ an, const int* __restrict__ nbr,
    const float* __restrict__ disp, const float* __restrict__ Wsp,
    const float* __restrict__ norm, int E)
{
    __shared__ float sYe[8][32];
    __shared__ float sG[8][16];
    int w = threadIdx.x >> 5, lane = threadIdx.x & 31;
    int e = blockIdx.x*8 + w;
    if (e >= E) return;

    int i = __ldg(nbr + 2*e), j = __ldg(nbr + 2*e + 1);
    float dx = __ldg(disp+3*e), dy = __ldg(disp+3*e+1), dz = __ldg(disp+3*e+2);
    float r = sqrtf(dx*dx + dy*dy + dz*dz + 1e-12f);
    float inv = 1.0f/r;
    float x = dx*inv, y = dy*inv, z = dz*inv;

    float t = fminf(r*0.2f, 1.0f);
    float fc = 0.5f*(cosf(3.14159265358979f*t) + 1.0f);
    float rb = 0.0f;
    if (lane < 16) {
        float d = r - (float)lane*(1.0f/3.0f);
        rb = __expf(-10.24f*d*d)*fc;
    }

    int Z = __ldg(an + j);
    const float* Wr = Wsp + (size_t)Z*256;
    float g = 0.0f;
    #pragma unroll
    for (int k=0;k<16;k++) {
        float rk = __shfl_sync(0xffffffffu, rb, k);
        float wv = (lane<16) ? __ldg(Wr + k*16 + lane) : 0.0f;
        g = fmaf(rk, wv, g);
    }
    if (lane < 16) sG[w][lane] = g / __ldg(norm);

    float x2=x*x, y2=y*y, z2=z*z;
    if (lane == 0) {
        float* S = sYe[w];
        S[0]=0.28209479177387814f;
        S[1]=0.4886025119029199f*y;  S[2]=0.4886025119029199f*z;  S[3]=0.4886025119029199f*x;
        S[4]=1.0925484305920792f*x*y; S[5]=1.0925484305920792f*y*z;
        S[6]=0.31539156525252005f*(3.f*z2-1.f);
        S[7]=1.0925484305920792f*x*z; S[8]=0.5462742152960396f*(x2-y2);
        S[9]=0.5900435899266435f*y*(3.f*x2-y2);
        S[10]=2.890611442640554f*x*y*z;
        S[11]=0.4570457994644658f*y*(5.f*z2-1.f);
        S[12]=0.3731763325901154f*z*(5.f*z2-3.f);
        S[13]=0.4570457994644658f*x*(5.f*z2-1.f);
        S[14]=1.445305721320277f*z*(x2-y2);
        S[15]=0.5900435899266435f*x*(x2-3.f*y2);
        S[16]=2.5033429417967046f*x*y*(x2-y2);
        S[17]=1.7701307697799304f*y*z*(3.f*x2-y2);
        S[18]=0.9461746957575601f*x*y*(7.f*z2-1.f);
        S[19]=0.6690465435572892f*y*z*(7.f*z2-3.f);
        S[20]=0.10578554691520431f*(35.f*z2*z2-30.f*z2+3.f);
        S[21]=0.6690465435572892f*x*z*(7.f*z2-3.f);
        S[22]=0.47308734787878004f*(x2-y2)*(7.f*z2-1.f);
        S[23]=1.7701307697799304f*x*z*(x2-3.f*y2);
        S[24]=0.6258357354491761f*(x2*x2-6.f*x2*y2+y2*y2);
    }
    __syncwarp();

    size_t base = (size_t)i*400;
    #pragma unroll
    for (int it=0; it<13; it++) {
        int tt = lane + it*32;
        if (tt < 400)
            atomicAdd(&g_Y0[base + tt], sYe[w][tt>>4] * sG[w][tt&15]);
    }
}

// ------------------------- dd block -----------------------------------------
// One weight stream serves all 2L+1 lm rows of a (p,L) block.
// yrow: first row of the block (+ q*YS + f); W1/W2 pre-offset by lane2;
// oA/oB pre-offset to (lm=L*L, parity, lane2); q stride 128.
template<int L, int YS>
__device__ __forceinline__ void dd_block(const float* __restrict__ yrow,
    float* oA, float* oB,
    const float* __restrict__ W1, const float* __restrict__ W2,
    int f0, int fc)
{
    constexpr int NL = 2*L+1;
    ull aA[NL], aB[NL];
    #pragma unroll
    for (int q=0;q<NL;q++){ aA[q]=0ull; aB[q]=0ull; }
    for (int f=f0; f<f0+fc; f+=2) {
        ull w1a = ld2g(W1 + f*64);
        ull w1b = ld2g(W1 + f*64 + 64);
        ull w2a = ld2g(W2 + f*64);
        ull w2b = ld2g(W2 + f*64 + 64);
        #pragma unroll
        for (int q=0;q<NL;q++) {
            ull yp = ld2s(yrow + q*YS + f);
            unsigned ylo, yhi;
            asm("mov.b64 {%0,%1}, %2;" : "=r"(ylo), "=r"(yhi) : "l"(yp));
            ull ys0, ys1; SPLAT2(ys0, ylo); SPLAT2(ys1, yhi);
            FMA2(aA[q], ys0, w1a, aA[q]);
            FMA2(aA[q], ys1, w1b, aA[q]);
            FMA2(aB[q], ys0, w2a, aB[q]);
            FMA2(aB[q], ys1, w2b, aB[q]);
        }
    }
    #pragma unroll
    for (int q=0;q<NL;q++) {
        float2 fa = unp(aA[q]), fb = unp(aB[q]);
        atomicAdd(oA + q*128,     fa.x);
        atomicAdd(oA + q*128 + 1, fa.y);
        atomicAdd(oB + q*128,     fb.x);
        atomicAdd(oB + q*128 + 1, fb.y);
    }
}

// ------------------------- atom kernel --------------------------------------
// smem layouts (floats):
//  sy0 [25 lm][16]        sa/sb/sy1/sy2 [25 lm][2 parity][64 ch]
__global__ __launch_bounds__(256, 3) void atom_kernel(
    const int* __restrict__ an,
    const float* __restrict__ emb, const float* __restrict__ W_et,
    const float* __restrict__ b_et,
    const float* __restrict__ t0W1, const float* __restrict__ t0W2,
    const float* __restrict__ t0wp,
    const float* __restrict__ t1W1, const float* __restrict__ t1W2,
    const float* __restrict__ t1wp,
    const float* __restrict__ wfu, float* __restrict__ out, int N)
{
    extern __shared__ float sm[];
    float* sy0  = sm;           // 400
    float* sa   = sm + 400;     // 3200
    float* sb   = sa + 3200;    // 3200
    float* sy1  = sb + 3200;    // 3200
    float* sy2  = sy1 + 3200;   // 3200
    float* ste  = sy2 + 3200;   // 144
    float* semb = ste + 144;    // 64

    int n = blockIdx.x;
    if (n >= N) return;
    int tid = threadIdx.x;
    int w = tid >> 5, lane = tid & 31;
    int lane2 = lane * 2;

    // ---- P1: loads + zero buffers ----
    for (int t = tid; t < 400; t += 256) sy0[t] = g_Y0[(size_t)n*400 + t];
    if (tid < 64) {
        int Z = __ldg(an + n);
        semb[tid] = __ldg(emb + (size_t)Z*64 + tid);
    }
    for (int t = tid; t < 3200; t += 256) { sa[t]=0.f; sb[t]=0.f; sy1[t]=0.f; sy2[t]=0.f; }
    __syncthreads();

    // ---- P2: dd0 (block items, parity0) + te ----
    for (int it = c_dd0Start[w]; it < c_dd0Start[w+1]; it++) {
        unsigned I = c_dd0Item[it];
        int f0 = I & 255, fc = (I>>8)&255, L = (I>>16)&7;
        const float* W1 = t0W1 + L*1024 + lane2;
        const float* W2 = t0W2 + L*1024 + lane2;
        const float* yrow = sy0 + L*L*16;
        float* oA = sa + L*L*128 + lane2;
        float* oB = sb + L*L*128 + lane2;
        switch (L) {
            case 0: dd_block<0,16>(yrow,oA,oB,W1,W2,f0,fc); break;
            case 1: dd_block<1,16>(yrow,oA,oB,W1,W2,f0,fc); break;
            case 2: dd_block<2,16>(yrow,oA,oB,W1,W2,f0,fc); break;
            case 3: dd_block<3,16>(yrow,oA,oB,W1,W2,f0,fc); break;
            default: dd_block<4,16>(yrow,oA,oB,W1,W2,f0,fc); break;
        }
    }
    if (tid < 144) {
        float acc = __ldg(b_et + tid);
        #pragma unroll 8
        for (int d = 0; d < 64; d++)
            acc = fmaf(semb[d], __ldg(W_et + d*144 + tid), acc);
        ste[tid] = acc;
    }
    __syncthreads();

    // ---- P3: tp0 (layer 0, only parity-0 inputs nonzero) ----
    {
        int g0 = c_sliceStart[w], g1 = c_sliceStart[w+1];
        const float* Abase = sa + lane2;
        const float* Bbase = sb + lane2;
        for (int gi = g0; gi < g1; gi++) {
            uint2 G = __ldg(&g_grp[gi]);
            int start = G.x & 0xFFFF, cnt = (int)(G.x >> 16);
            int ic = G.y & 31, s = (G.y>>5)&1, path = (int)(G.y>>8);
            ull s00 = 0, a0 = 0;
            for (int k = 0; k < cnt; k++) {
                uint2 Ee = __ldg(&g_ent[start+k]);
                unsigned xi = Ee.x;
                if (xi & 0x8000u)
                    a0 = ld2s(Abase + (xi & 0x7FFFu));
                ull b0 = ld2s(Bbase + (xi >> 16));
                ull vv; SPLAT2(vv, Ee.y);
                ull p00; MUL2(p00, a0, b0);
                FMA2(s00, vv, p00, s00);
            }
            float2 t00 = unp(s00);
            float2 w00 = *(const float2*)(t0wp + path*256 + lane2);
            atomicAdd(&sy1[ic*128 + s*64 + lane2],     w00.x * t00.x);
            atomicAdd(&sy1[ic*128 + s*64 + lane2 + 1], w00.y * t00.y);
        }
    }
    __syncthreads();

    // ---- P4: re-zero dd buffers ----
    for (int t = tid; t < 3200; t += 256) { sa[t]=0.f; sb[t]=0.f; }
    __syncthreads();

    // ---- P5: dd1 (block items, both parities) ----
    for (int it = c_dd1Start[w]; it < c_dd1Start[w+1]; it++) {
        unsigned I = c_dd1Item[it];
        int f0 = I & 255, fc = (I>>8)&255, L = (I>>16)&7, p = (I>>19)&1;
        const float* W1 = t1W1 + p*20480 + L*4096 + lane2;
        const float* W2 = t1W2 + p*20480 + L*4096 + lane2;
        const float* yrow = sy1 + L*L*128 + p*64;
        float* oA = sa + L*L*128 + p*64 + lane2;
        float* oB = sb + L*L*128 + p*64 + lane2;
        switch (L) {
            case 0: dd_block<0,128>(yrow,oA,oB,W1,W2,f0,fc); break;
            case 1: dd_block<1,128>(yrow,oA,oB,W1,W2,f0,fc); break;
            case 2: dd_block<2,128>(yrow,oA,oB,W1,W2,f0,fc); break;
            case 3: dd_block<3,128>(yrow,oA,oB,W1,W2,f0,fc); break;
            default: dd_block<4,128>(yrow,oA,oB,W1,W2,f0,fc); break;
        }
    }
    __syncthreads();

    // ---- P6: tp1 (full, both parities) ----
    {
        int g0 = c_sliceStart[w], g1 = c_sliceStart[w+1];
        const float* Abase = sa + lane2;
        const float* Bbase = sb + lane2;
        for (int gi = g0; gi < g1; gi++) {
            uint2 G = __ldg(&g_grp[gi]);
            int start = G.x & 0xFFFF, cnt = (int)(G.x >> 16);
            int ic = G.y & 31, s = (G.y>>5)&1, path = (int)(G.y>>8);
            ull s00 = 0, s11 = 0, s01 = 0, s10 = 0;
            ull a0 = 0, a1 = 0;
            for (int k = 0; k < cnt; k++) {
                uint2 Ee = __ldg(&g_ent[start+k]);
                unsigned xi = Ee.x;
                if (xi & 0x8000u) {
                    const float* A = Abase + (xi & 0x7FFFu);
                    a0 = ld2s(A);
                    a1 = ld2s(A + 64);
                }
                const float* B = Bbase + (xi >> 16);
                ull b0 = ld2s(B), b1 = ld2s(B + 64);
                ull vv; SPLAT2(vv, Ee.y);
                ull p00, p11, p01, p10;
                MUL2(p00, a0, b0); MUL2(p11, a1, b1);
                MUL2(p01, a0, b1); MUL2(p10, a1, b0);
                FMA2(s00, vv, p00, s00);
                FMA2(s11, vv, p11, s11);
                FMA2(s01, vv, p01, s01);
                FMA2(s10, vv, p10, s10);
            }
            const float* wq = t1wp + path*256 + lane2;
            float2 w00 = *(const float2*)(wq);
            float2 w01 = *(const float2*)(wq + 64);
            float2 w10 = *(const float2*)(wq + 128);
            float2 w11 = *(const float2*)(wq + 192);
            float2 t00 = unp(s00), t11 = unp(s11), t01 = unp(s01), t10 = unp(s10);
            float evx = fmaf(w00.x, t00.x, w11.x * t11.x);
            float evy = fmaf(w00.y, t00.y, w11.y * t11.y);
            float odx = fmaf(w01.x, t01.x, w10.x * t10.x);
            float ody = fmaf(w01.y, t01.y, w10.y * t10.y);
            atomicAdd(&sy2[ic*128 + s*64 + lane2],         evx);
            atomicAdd(&sy2[ic*128 + s*64 + lane2 + 1],     evy);
            atomicAdd(&sy2[ic*128 + (1-s)*64 + lane2],     odx);
            atomicAdd(&sy2[ic*128 + (1-s)*64 + lane2 + 1], ody);
        }
    }
    __syncthreads();

    // ---- P7: fused epilogue + mish ----
    for (int t = tid; t < 7200; t += 256) {
        int p = t/3600, rem = t - p*3600;
        int lm = rem/144, c = rem - lm*144;
        float feat;
        if (c < 16)       feat = p ? 0.f : sy0[lm*16 + c];
        else if (c < 80)  feat = sy1[lm*128 + p*64 + (c-16)];
        else              feat = sy2[lm*128 + p*64 + (c-80)];
        int dg = lm>=16?4: lm>=9?3: lm>=4?2: lm>=1?1:0;
        float v = ste[c] * feat * __ldg(wfu + p*720 + dg*144 + c);
        if (p==0 && lm==0) v += ste[c];
        float ev = __expf(v);
        float w1v = 1.f + ev;
        float wv  = w1v*w1v;
        float rr  = (v > 20.f) ? 2.f*v : v * __fdividef(2.f*wv, wv + 1.f);
        out[(size_t)n*7200 + t] = rr;
    }
}

// ------------------------- launch ------------------------------------------
extern "C" void kernel_launch(void* const* d_in, const int* in_sizes, int n_in,
                              void* d_out, int out_size)
{
    tab::build();

    const int*   an   = (const int*)d_in[0];
    const int*   nbr  = (const int*)d_in[1];
    const float* disp = (const float*)d_in[2];
    const float* Wsp  = (const float*)d_in[3];
    const float* emb  = (const float*)d_in[4];
    const float* W_et = (const float*)d_in[5];
    const float* b_et = (const float*)d_in[6];
    const float* norm = (const float*)d_in[7];
    const float* t0W1 = (const float*)d_in[8];
    const float* t0W2 = (const float*)d_in[9];
    const float* t0wp = (const float*)d_in[10];
    const float* t1W1 = (const float*)d_in[11];
    const float* t1W2 = (const float*)d_in[12];
    const float* t1wp = (const float*)d_in[13];
    const float* wfu  = (const float*)d_in[14];
    float* out = (float*)d_out;

    int N = in_sizes[0];
    int E = in_sizes[1] / 2;

    cudaMemcpyToSymbolAsync(g_ent, tab::h_ent, tab::nent*sizeof(uint2),
                            0, cudaMemcpyHostToDevice, 0);
    cudaMemcpyToSymbolAsync(g_grp, tab::h_grp, tab::ngrp*sizeof(uint2),
                            0, cudaMemcpyHostToDevice, 0);
    cudaMemcpyToSymbolAsync(c_sliceStart, tab::h_sliceStart, (NSLICE+1)*sizeof(int),
                            0, cudaMemcpyHostToDevice, 0);
    cudaMemcpyToSymbolAsync(c_dd0Start, tab::h_dd0Start, (NSLICE+1)*sizeof(int),
                            0, cudaMemcpyHostToDevice, 0);
    cudaMemcpyToSymbolAsync(c_dd1Start, tab::h_dd1Start, (NSLICE+1)*sizeof(int),
                            0, cudaMemcpyHostToDevice, 0);
    cudaMemcpyToSymbolAsync(c_dd0Item, tab::h_dd0Item, sizeof(tab::h_dd0Item),
                            0, cudaMemcpyHostToDevice, 0);
    cudaMemcpyToSymbolAsync(c_dd1Item, tab::h_dd1Item, sizeof(tab::h_dd1Item),
                            0, cudaMemcpyHostToDevice, 0);

    void* y0ptr = nullptr;
    cudaGetSymbolAddress(&y0ptr, g_Y0);
    cudaMemsetAsync(y0ptr, 0, (size_t)N*400*sizeof(float), 0);

    edge_kernel<<<(E + 7)/8, 256>>>(an, nbr, disp, Wsp, norm, E);

    static bool attr_done = false;
    size_t smem = 13408 * sizeof(float);
    if (!attr_done) {
        cudaFuncSetAttribute(atom_kernel, cudaFuncAttributeMaxDynamicSharedMemorySize,
                             (int)smem);
        attr_done = true;
    }
    atom_kernel<<<N, 256, smem>>>(an, emb, W_et, b_et, t0W1, t0W2, t0wp,
                                  t1W1, t1W2, t1wp, wfu, out, N);
}

// round 9
// speedup vs baseline: 1.0182x; 1.0182x over previous
#include <cuda_runtime.h>
#include <cmath>
#include <cstdint>
#include <cstring>
#include <complex>
#include <vector>
#include <algorithm>

#define MAXE 7000
#define MAXG 600
#define MAXN 10000
#define NSLICE 8

static __device__ float g_Y0[(size_t)MAXN * 400];
static __device__ uint2 g_ent[MAXE];
static __device__ uint2 g_grp[MAXG];
__constant__ int c_sliceStart[NSLICE + 1];
__constant__ int c_dd0Start[NSLICE + 1];
__constant__ int c_dd1Start[NSLICE + 1];
__constant__ unsigned c_dd0Item[16];
__constant__ unsigned c_dd1Item[24];

typedef unsigned long long ull;

#define FMA2(d, a, b, c) asm("fma.rn.f32x2 %0, %1, %2, %3;" : "=l"(d) : "l"(a), "l"(b), "l"(c))
#define MUL2(d, a, b)    asm("mul.rn.f32x2 %0, %1, %2;"     : "=l"(d) : "l"(a), "l"(b))
#define SPLAT2(d, s)     asm("mov.b64 %0, {%1, %1};"        : "=l"(d) : "r"(s))

__device__ __forceinline__ ull ld2s(const float* p) { return *(const ull*)p; }
__device__ __forceinline__ ull ld2g(const float* p) { return __ldg((const ull*)p); }
__device__ __forceinline__ float2 unp(ull v) { float2 f; memcpy(&f, &v, 8); return f; }

// ------------------------- host tables -------------------------------------
namespace tab {
static int nent = 0, ngrp = 0;
static uint2 h_ent[MAXE];
static uint2 h_grp[MAXG];
static int h_sliceStart[NSLICE + 1];
static unsigned h_dd0Item[16], h_dd1Item[24];
static int h_dd0Start[NSLICE + 1], h_dd1Start[NSLICE + 1];
static bool built = false;

static double lf(int n) { return lgamma((double)n + 1.0); }

static double cgc(int l1, int m1, int l2, int m2, int l3, int m3) {
    if (m1 + m2 != m3 || l3 < abs(l1 - l2) || l3 > l1 + l2) return 0.0;
    double pre = 0.5 * (lf(l1+l2-l3) + lf(l1-l2+l3) + lf(-l1+l2+l3) - lf(l1+l2+l3+1)
                 + lf(l1+m1) + lf(l1-m1) + lf(l2+m2) + lf(l2-m2) + lf(l3+m3) + lf(l3-m3));
    int kmin = std::max(0, std::max(l2-l3-m1, l1-l3+m2));
    int kmax = std::min(l1+l2-l3, std::min(l1-m1, l2+m2));
    double s = 0.0;
    for (int k = kmin; k <= kmax; k++) {
        double ln = lf(k) + lf(l1+l2-l3-k) + lf(l1-m1-k) + lf(l2+m2-k)
                  + lf(l3-l2+m1+k) + lf(l3-l1-m2+k);
        s += ((k & 1) ? -1.0 : 1.0) * exp(pre - ln);
    }
    return sqrt(2.0*l3+1.0) * s;
}

static int degof(int lm){ return lm>=16?4: lm>=9?3: lm>=4?2: lm>=1?1:0; }

struct Rent { int path, ic, ia, ib; double v; };
static std::complex<double> Cc[25][25][25];

static void build() {
    if (built) return;
    built = true;
    int pid[5][5][5];
    for (int a=0;a<5;a++)for(int b=0;b<5;b++)for(int c=0;c<5;c++) pid[a][b][c]=-1;
    int np = 0;
    for (int l1=0;l1<=4;l1++)
        for (int l2=0;l2<=4;l2++)
            for (int l3=abs(l1-l2); l3<=std::min(4,l1+l2); l3++)
                pid[l1][l2][l3] = np++;

    for (int l1=0;l1<=4;l1++)
        for (int l2=0;l2<=4;l2++)
            for (int l3=abs(l1-l2); l3<=std::min(4,l1+l2); l3++)
                for (int m1=-l1;m1<=l1;m1++)
                    for (int m2=-l2;m2<=l2;m2++) {
                        int m3 = m1+m2;
                        if (abs(m3) <= l3)
                            Cc[l1*l1+l1+m1][l2*l2+l2+m2][l3*l3+l3+m3] = cgc(l1,m1,l2,m2,l3,m3);
                    }

    const double s2 = 1.0/sqrt(2.0);
    std::complex<double> Uv[25][2]; int Uc[25][2]; int Un[25];
    for (int l=0;l<=4;l++) {
        int off = l*l+l;
        Un[off]=1; Uc[off][0]=off; Uv[off][0]={1,0}; Uc[off][1]=off; Uv[off][1]={0,0};
        for (int m=1;m<=l;m++) {
            double sg = (m&1)?-1.0:1.0;
            Un[off+m]=2;
            Uc[off+m][0]=off+m; Uv[off+m][0]={sg*s2,0};
            Uc[off+m][1]=off-m; Uv[off+m][1]={s2,0};
            Un[off-m]=2;
            Uc[off-m][0]=off-m; Uv[off-m][0]={0,s2};
            Uc[off-m][1]=off+m; Uv[off-m][1]={0,-sg*s2};
        }
    }

    std::vector<Rent> es; es.reserve(5000);
    for (int i=0;i<25;i++)
        for (int j=0;j<25;j++)
            for (int k=0;k<25;k++) {
                std::complex<double> T(0,0);
                for (int a=0;a<Un[i];a++)
                    for (int b=0;b<Un[j];b++)
                        for (int c=0;c<Un[k];c++)
                            T += Uv[i][a]*Uv[j][b]*std::conj(Uv[k][c])*Cc[Uc[i][a]][Uc[j][b]][Uc[k][c]];
                double C = T.real() + T.imag();
                if (std::fabs(C) < 1e-12) continue;
                int p = pid[degof(i)][degof(j)][degof(k)];
                if (p < 0) continue;
                es.push_back({p, k, i, j, C});
            }

    std::sort(es.begin(), es.end(), [](const Rent&a, const Rent&b){
        if (a.path!=b.path) return a.path<b.path;
        if (a.ic!=b.ic) return a.ic<b.ic;
        if (a.ia!=b.ia) return a.ia<b.ia;
        return a.ib<b.ib; });

    nent = (int)std::min((size_t)MAXE, es.size());

    // groups on (path, ic) boundaries; "reload-a" flag on bit 15
    std::vector<int> gstart, gcnt, gic, gss, gpath;
    int lastp=-1, lastic=-1, lastia=-1;
    for (int e=0;e<nent;e++) {
        bool newgrp = (es[e].path!=lastp || es[e].ic!=lastic);
        if (newgrp) {
            lastp = es[e].path; lastic = es[e].ic; lastia = -1;
            gstart.push_back(e); gcnt.push_back(0);
            gic.push_back(es[e].ic);
            gss.push_back((degof(es[e].ia)+degof(es[e].ib)+degof(es[e].ic))&1);
            gpath.push_back(es[e].path);
        }
        gcnt.back()++;
        unsigned iao = (unsigned)(es[e].ia*128);
        if (es[e].ia != lastia) { iao |= 0x8000u; lastia = es[e].ia; }
        h_ent[e].x = iao | ((unsigned)(es[e].ib*128)<<16);
        float vv = (float)es[e].v;
        unsigned vb; memcpy(&vb, &vv, 4);
        h_ent[e].y = vb;
    }
    int NG = (int)gstart.size();

    // greedy TP slice assignment over NSLICE warps
    {
        std::vector<int> ord(NG);
        for (int g=0; g<NG; g++) ord[g]=g;
        std::sort(ord.begin(), ord.end(), [&](int a, int b){ return gcnt[a]>gcnt[b]; });
        std::vector<int> sl(NG); long load[NSLICE]={0};
        for (int oi=0; oi<NG; oi++) {
            int g = ord[oi];
            int m=0;
            for (int k=1;k<NSLICE;k++) if (load[k]<load[m]) m=k;
            sl[g]=m; load[m]+=gcnt[g]+4;
        }
        int pos=0;
        for (int s=0;s<NSLICE;s++) {
            h_sliceStart[s]=pos;
            for (int g=0; g<NG && pos<MAXG; g++) if (sl[g]==s) {
                h_grp[pos].x = (unsigned)gstart[g] | ((unsigned)gcnt[g]<<16);
                h_grp[pos].y = (unsigned)gic[g] | ((unsigned)gss[g]<<5) | ((unsigned)gpath[g]<<8);
                pos++;
            }
        }
        h_sliceStart[NSLICE]=pos; ngrp=pos;
    }

    // dd items: enc = L | p<<3 | q0<<4 | qn<<8 ; rows chunked to <=5
    struct It { unsigned enc; int cost; };
    auto pack=[](int p,int L,int q0,int qn){
        return (unsigned)L | ((unsigned)p<<3) | ((unsigned)q0<<4) | ((unsigned)qn<<8);
    };
    auto greedy=[&](std::vector<It>& v, unsigned* items, int* starts){
        std::sort(v.begin(), v.end(), [](const It&a, const It&b){ return a.cost>b.cost; });
        long load[NSLICE]={0};
        std::vector<int> asg(v.size());
        for (size_t i=0;i<v.size();i++) {
            int m=0;
            for (int k=1;k<NSLICE;k++) if (load[k]<load[m]) m=k;
            asg[i]=m; load[m]+=v[i].cost;
        }
        int pos=0;
        for (int s=0;s<NSLICE;s++) {
            starts[s]=pos;
            for (size_t i=0;i<v.size();i++) if (asg[i]==s) items[pos++]=v[i].enc;
        }
        starts[NSLICE]=pos;
    };
    {
        std::vector<It> v1;
        for (int p=0;p<2;p++)
            for (int L=0;L<5;L++) {
                int NL = 2*L+1;
                for (int q0=0; q0<NL; q0+=5) {
                    int qn = std::min(5, NL-q0);
                    v1.push_back({pack(p,L,q0,qn), qn*64});
                }
            }
        greedy(v1, h_dd1Item, h_dd1Start);
        std::vector<It> v0;
        for (int L=0;L<5;L++) {
            int NL = 2*L+1;
            for (int q0=0; q0<NL; q0+=5) {
                int qn = std::min(5, NL-q0);
                v0.push_back({pack(0,L,q0,qn), qn*16});
            }
        }
        greedy(v0, h_dd0Item, h_dd0Start);
    }
}
} // namespace tab

// ------------------------- edge kernel --------------------------------------
__global__ __launch_bounds__(256) void edge_kernel(
    const int* __restrict__ an, const int* __restrict__ nbr,
    const float* __restrict__ disp, const float* __restrict__ Wsp,
    const float* __restrict__ norm, int E)
{
    __shared__ float sYe[8][32];
    __shared__ float sG[8][16];
    int w = threadIdx.x >> 5, lane = threadIdx.x & 31;
    int e = blockIdx.x*8 + w;
    if (e >= E) return;

    int i = __ldg(nbr + 2*e), j = __ldg(nbr + 2*e + 1);
    float dx = __ldg(disp+3*e), dy = __ldg(disp+3*e+1), dz = __ldg(disp+3*e+2);
    float r = sqrtf(dx*dx + dy*dy + dz*dz + 1e-12f);
    float inv = 1.0f/r;
    float x = dx*inv, y = dy*inv, z = dz*inv;

    float t = fminf(r*0.2f, 1.0f);
    float fc = 0.5f*(cosf(3.14159265358979f*t) + 1.0f);
    float rb = 0.0f;
    if (lane < 16) {
        float d = r - (float)lane*(1.0f/3.0f);
        rb = __expf(-10.24f*d*d)*fc;
    }

    int Z = __ldg(an + j);
    const float* Wr = Wsp + (size_t)Z*256;
    float g = 0.0f;
    #pragma unroll
    for (int k=0;k<16;k++) {
        float rk = __shfl_sync(0xffffffffu, rb, k);
        float wv = (lane<16) ? __ldg(Wr + k*16 + lane) : 0.0f;
        g = fmaf(rk, wv, g);
    }
    if (lane < 16) sG[w][lane] = g / __ldg(norm);

    float x2=x*x, y2=y*y, z2=z*z;
    if (lane == 0) {
        float* S = sYe[w];
        S[0]=0.28209479177387814f;
        S[1]=0.4886025119029199f*y;  S[2]=0.4886025119029199f*z;  S[3]=0.4886025119029199f*x;
        S[4]=1.0925484305920792f*x*y; S[5]=1.0925484305920792f*y*z;
        S[6]=0.31539156525252005f*(3.f*z2-1.f);
        S[7]=1.0925484305920792f*x*z; S[8]=0.5462742152960396f*(x2-y2);
        S[9]=0.5900435899266435f*y*(3.f*x2-y2);
        S[10]=2.890611442640554f*x*y*z;
        S[11]=0.4570457994644658f*y*(5.f*z2-1.f);
        S[12]=0.3731763325901154f*z*(5.f*z2-3.f);
        S[13]=0.4570457994644658f*x*(5.f*z2-1.f);
        S[14]=1.445305721320277f*z*(x2-y2);
        S[15]=0.5900435899266435f*x*(x2-3.f*y2);
        S[16]=2.5033429417967046f*x*y*(x2-y2);
        S[17]=1.7701307697799304f*y*z*(3.f*x2-y2);
        S[18]=0.9461746957575601f*x*y*(7.f*z2-1.f);
        S[19]=0.6690465435572892f*y*z*(7.f*z2-3.f);
        S[20]=0.10578554691520431f*(35.f*z2*z2-30.f*z2+3.f);
        S[21]=0.6690465435572892f*x*z*(7.f*z2-3.f);
        S[22]=0.47308734787878004f*(x2-y2)*(7.f*z2-1.f);
        S[23]=1.7701307697799304f*x*z*(x2-3.f*y2);
        S[24]=0.6258357354491761f*(x2*x2-6.f*x2*y2+y2*y2);
    }
    __syncwarp();

    size_t base = (size_t)i*400;
    #pragma unroll
    for (int it=0; it<13; it++) {
        int tt = lane + it*32;
        if (tt < 400)
            atomicAdd(&g_Y0[base + tt], sYe[w][tt>>4] * sG[w][tt&15]);
    }
}

// ------------------------- dd block -----------------------------------------
// yrow: input row base (stride YS per row). W1/W2 pre-offset by lane*2.
// oA/oB: packed output slot for row q0 (stride 128 per row). Plain stores.
template<int YS>
__device__ __forceinline__ void dd_block(const float* __restrict__ yrow,
    float* oA, float* oB,
    const float* __restrict__ W1, const float* __restrict__ W2,
    int qn, int fc)
{
    ull aA[5], aB[5];
    #pragma unroll
    for (int q=0;q<5;q++){ aA[q]=0ull; aB[q]=0ull; }
    for (int f=0; f<fc; f+=2) {
        ull w1a = ld2g(W1 + f*64);
        ull w1b = ld2g(W1 + f*64 + 64);
        ull w2a = ld2g(W2 + f*64);
        ull w2b = ld2g(W2 + f*64 + 64);
        #pragma unroll
        for (int q=0;q<5;q++) {
            if (q < qn) {
                ull yp = ld2s(yrow + q*YS + f);   // uniform -> broadcast
                unsigned ylo, yhi;
                asm("mov.b64 {%0,%1}, %2;" : "=r"(ylo), "=r"(yhi) : "l"(yp));
                ull ys0, ys1; SPLAT2(ys0, ylo); SPLAT2(ys1, yhi);
                FMA2(aA[q], ys0, w1a, aA[q]);
                FMA2(aA[q], ys1, w1b, aA[q]);
                FMA2(aB[q], ys0, w2a, aB[q]);
                FMA2(aB[q], ys1, w2b, aB[q]);
            }
        }
    }
    #pragma unroll
    for (int q=0;q<5;q++) {
        if (q < qn) {
            *(ull*)(oA + q*128) = aA[q];
            *(ull*)(oB + q*128) = aB[q];
        }
    }
}

// ------------------------- atom kernel --------------------------------------
// smem layouts (floats):
//  sy0 [25][16]
//  sa/sb packed: [25 lm][32 ch2][p0c0,p0c1,p1c0,p1c1]   (3200 each)
//  sy1/sy2 plain: [25 lm][2 parity][64 ch]               (3200 each)
__global__ __launch_bounds__(256, 4) void atom_kernel(
    const int* __restrict__ an,
    const float* __restrict__ emb, const float* __restrict__ W_et,
    const float* __restrict__ b_et,
    const float* __restrict__ t0W1, const float* __restrict__ t0W2,
    const float* __restrict__ t0wp,
    const float* __restrict__ t1W1, const float* __restrict__ t1W2,
    const float* __restrict__ t1wp,
    const float* __restrict__ wfu, float* __restrict__ out, int N)
{
    extern __shared__ float sm[];
    float* sy0  = sm;           // 400
    float* sa   = sm + 400;     // 3200
    float* sb   = sa + 3200;    // 3200
    float* sy1  = sb + 3200;    // 3200
    float* sy2  = sy1 + 3200;   // 3200
    float* ste  = sy2 + 3200;   // 144
    float* semb = ste + 144;    // 64

    int n = blockIdx.x;
    if (n >= N) return;
    int tid = threadIdx.x;
    int w = tid >> 5, lane = tid & 31;
    int lane2 = lane * 2;
    int lane4 = lane * 4;

    // ---- P1: loads + zero TP outputs (sy1, sy2 contiguous) ----
    for (int t = tid; t < 400; t += 256) sy0[t] = g_Y0[(size_t)n*400 + t];
    if (tid < 64) {
        int Z = __ldg(an + n);
        semb[tid] = __ldg(emb + (size_t)Z*64 + tid);
    }
    {
        ull* z = (ull*)sy1;
        for (int t = tid; t < 3200; t += 256) z[t] = 0ull;
    }
    __syncthreads();

    // ---- P2: dd0 (exclusive row chunks, parity0, fc=16) + te ----
    for (int it = c_dd0Start[w]; it < c_dd0Start[w+1]; it++) {
        unsigned I = c_dd0Item[it];
        int L = I & 7, q0 = (I>>4)&15, qn = (I>>8)&15;
        int lm0 = L*L + q0;
        dd_block<16>(sy0 + lm0*16,
                     sa + lm0*128 + lane4, sb + lm0*128 + lane4,
                     t0W1 + L*1024 + lane2, t0W2 + L*1024 + lane2,
                     qn, 16);
    }
    if (tid < 144) {
        float acc = __ldg(b_et + tid);
        #pragma unroll 8
        for (int d = 0; d < 64; d++)
            acc = fmaf(semb[d], __ldg(W_et + d*144 + tid), acc);
        ste[tid] = acc;
    }
    __syncthreads();

    // ---- P3: tp0 (parity0 pairs only; packed LDS.64) ----
    {
        int g0 = c_sliceStart[w], g1 = c_sliceStart[w+1];
        const float* Abase = sa + lane4;
        const float* Bbase = sb + lane4;
        for (int gi = g0; gi < g1; gi++) {
            uint2 G = __ldg(&g_grp[gi]);
            int start = G.x & 0xFFFF, cnt = (int)(G.x >> 16);
            int ic = G.y & 31, s = (G.y>>5)&1, path = (int)(G.y>>8);
            ull s00 = 0, a0 = 0;
            for (int k = 0; k < cnt; k++) {
                uint2 Ee = __ldg(&g_ent[start+k]);
                unsigned xi = Ee.x;
                if (xi & 0x8000u)
                    a0 = ld2s(Abase + (xi & 0x7FFFu));
                ull b0 = ld2s(Bbase + (xi >> 16));
                ull vv; SPLAT2(vv, Ee.y);
                ull p00; MUL2(p00, a0, b0);
                FMA2(s00, vv, p00, s00);
            }
            float2 t00 = unp(s00);
            float2 w00 = *(const float2*)(t0wp + path*256 + lane2);
            atomicAdd(&sy1[ic*128 + s*64 + lane2],     w00.x * t00.x);
            atomicAdd(&sy1[ic*128 + s*64 + lane2 + 1], w00.y * t00.y);
        }
    }
    __syncthreads();

    // ---- P4: dd1 (exclusive row chunks, both parities, fc=64; plain stores) ----
    for (int it = c_dd1Start[w]; it < c_dd1Start[w+1]; it++) {
        unsigned I = c_dd1Item[it];
        int L = I & 7, p = (I>>3)&1, q0 = (I>>4)&15, qn = (I>>8)&15;
        int lm0 = L*L + q0;
        dd_block<128>(sy1 + lm0*128 + p*64,
                      sa + lm0*128 + lane4 + 2*p, sb + lm0*128 + lane4 + 2*p,
                      t1W1 + p*20480 + L*4096 + lane2,
                      t1W2 + p*20480 + L*4096 + lane2,
                      qn, 64);
    }
    __syncthreads();

    // ---- P5: tp1 (both parities; packed LDS.128) ----
    {
        int g0 = c_sliceStart[w], g1 = c_sliceStart[w+1];
        const float* Abase = sa + lane4;
        const float* Bbase = sb + lane4;
        for (int gi = g0; gi < g1; gi++) {
            uint2 G = __ldg(&g_grp[gi]);
            int start = G.x & 0xFFFF, cnt = (int)(G.x >> 16);
            int ic = G.y & 31, s = (G.y>>5)&1, path = (int)(G.y>>8);
            ull s00 = 0, s11 = 0, s01 = 0, s10 = 0;
            ull a0 = 0, a1 = 0;
            for (int k = 0; k < cnt; k++) {
                uint2 Ee = __ldg(&g_ent[start+k]);
                unsigned xi = Ee.x;
                if (xi & 0x8000u) {
                    ulonglong2 av = *(const ulonglong2*)(Abase + (xi & 0x7FFFu));
                    a0 = av.x; a1 = av.y;
                }
                ulonglong2 bv = *(const ulonglong2*)(Bbase + (xi >> 16));
                ull b0 = bv.x, b1 = bv.y;
                ull vv; SPLAT2(vv, Ee.y);
                ull p00, p11, p01, p10;
                MUL2(p00, a0, b0); MUL2(p11, a1, b1);
                MUL2(p01, a0, b1); MUL2(p10, a1, b0);
                FMA2(s00, vv, p00, s00);
                FMA2(s11, vv, p11, s11);
                FMA2(s01, vv, p01, s01);
                FMA2(s10, vv, p10, s10);
            }
            const float* wq = t1wp + path*256 + lane2;
            float2 w00 = *(const float2*)(wq);
            float2 w01 = *(const float2*)(wq + 64);
            float2 w10 = *(const float2*)(wq + 128);
            float2 w11 = *(const float2*)(wq + 192);
            float2 t00 = unp(s00), t11 = unp(s11), t01 = unp(s01), t10 = unp(s10);
            float evx = fmaf(w00.x, t00.x, w11.x * t11.x);
            float evy = fmaf(w00.y, t00.y, w11.y * t11.y);
            float odx = fmaf(w01.x, t01.x, w10.x * t10.x);
            float ody = fmaf(w01.y, t01.y, w10.y * t10.y);
            atomicAdd(&sy2[ic*128 + s*64 + lane2],         evx);
            atomicAdd(&sy2[ic*128 + s*64 + lane2 + 1],     evy);
            atomicAdd(&sy2[ic*128 + (1-s)*64 + lane2],     odx);
            atomicAdd(&sy2[ic*128 + (1-s)*64 + lane2 + 1], ody);
        }
    }
    __syncthreads();

    // ---- P6: fused epilogue + mish ----
    for (int t = tid; t < 7200; t += 256) {
        int p = t/3600, rem = t - p*3600;
        int lm = rem/144, c = rem - lm*144;
        float feat;
        if (c < 16)       feat = p ? 0.f : sy0[lm*16 + c];
        else if (c < 80)  feat = sy1[lm*128 + p*64 + (c-16)];
        else              feat = sy2[lm*128 + p*64 + (c-80)];
        int dg = lm>=16?4: lm>=9?3: lm>=4?2: lm>=1?1:0;
        float v = ste[c] * feat * __ldg(wfu + p*720 + dg*144 + c);
        if (p==0 && lm==0) v += ste[c];
        float ev = __expf(v);
        float w1v = 1.f + ev;
        float wv  = w1v*w1v;
        float rr  = (v > 20.f) ? 2.f*v : v * __fdividef(2.f*wv, wv + 1.f);
        out[(size_t)n*7200 + t] = rr;
    }
}

// ------------------------- launch ------------------------------------------
extern "C" void kernel_launch(void* const* d_in, const int* in_sizes, int n_in,
                              void* d_out, int out_size)
{
    tab::build();

    const int*   an   = (const int*)d_in[0];
    const int*   nbr  = (const int*)d_in[1];
    const float* disp = (const float*)d_in[2];
    const float* Wsp  = (const float*)d_in[3];
    const float* emb  = (const float*)d_in[4];
    const float* W_et = (const float*)d_in[5];
    const float* b_et = (const float*)d_in[6];
    const float* norm = (const float*)d_in[7];
    const float* t0W1 = (const float*)d_in[8];
    const float* t0W2 = (const float*)d_in[9];
    const float* t0wp = (const float*)d_in[10];
    const float* t1W1 = (const float*)d_in[11];
    const float* t1W2 = (const float*)d_in[12];
    const float* t1wp = (const float*)d_in[13];
    const float* wfu  = (const float*)d_in[14];
    float* out = (float*)d_out;

    int N = in_sizes[0];
    int E = in_sizes[1] / 2;

    cudaMemcpyToSymbolAsync(g_ent, tab::h_ent, tab::nent*sizeof(uint2),
                            0, cudaMemcpyHostToDevice, 0);
    cudaMemcpyToSymbolAsync(g_grp, tab::h_grp, tab::ngrp*sizeof(uint2),
                            0, cudaMemcpyHostToDevice, 0);
    cudaMemcpyToSymbolAsync(c_sliceStart, tab::h_sliceStart, (NSLICE+1)*sizeof(int),
                            0, cudaMemcpyHostToDevice, 0);
    cudaMemcpyToSymbolAsync(c_dd0Start, tab::h_dd0Start, (NSLICE+1)*sizeof(int),
                            0, cudaMemcpyHostToDevice, 0);
    cudaMemcpyToSymbolAsync(c_dd1Start, tab::h_dd1Start, (NSLICE+1)*sizeof(int),
                            0, cudaMemcpyHostToDevice, 0);
    cudaMemcpyToSymbolAsync(c_dd0Item, tab::h_dd0Item, sizeof(tab::h_dd0Item),
                            0, cudaMemcpyHostToDevice, 0);
    cudaMemcpyToSymbolAsync(c_dd1Item, tab::h_dd1Item, sizeof(tab::h_dd1Item),
                            0, cudaMemcpyHostToDevice, 0);

    void* y0ptr = nullptr;
    cudaGetSymbolAddress(&y0ptr, g_Y0);
    cudaMemsetAsync(y0ptr, 0, (size_t)N*400*sizeof(float), 0);

    edge_kernel<<<(E + 7)/8, 256>>>(an, nbr, disp, Wsp, norm, E);

    static bool attr_done = false;
    size_t smem = 13408 * sizeof(float);
    if (!attr_done) {
        cudaFuncSetAttribute(atom_kernel, cudaFuncAttributeMaxDynamicSharedMemorySize,
                             (int)smem);
        attr_done = true;
    }
    atom_kernel<<<N, 256, smem>>>(an, emb, W_et, b_et, t0W1, t0W2, t0wp,
                                  t1W1, t1W2, t1wp, wfu, out, N);
}

// round 11
// speedup vs baseline: 1.1265x; 1.1063x over previous
#include <cuda_runtime.h>
#include <cmath>
#include <cstdint>
#include <cstring>
#include <complex>
#include <vector>
#include <algorithm>

#define MAXE 7000
#define MAXG 600
#define MAXN 10000
#define NSLICE 8

static __device__ float g_Y0[(size_t)MAXN * 400];
static __device__ uint2 g_ent[MAXE];
static __device__ uint2 g_grp[MAXG];
static __device__ float g_wpPack[65 * 256];
__constant__ int c_sliceStart[NSLICE + 1];
__constant__ int c_dd0Start[NSLICE + 1];
__constant__ int c_dd1Start[NSLICE + 1];
__constant__ unsigned c_dd0Item[16];
__constant__ unsigned c_dd1Item[24];

typedef unsigned long long ull;

#define FMA2(d, a, b, c) asm("fma.rn.f32x2 %0, %1, %2, %3;" : "=l"(d) : "l"(a), "l"(b), "l"(c))
#define MUL2(d, a, b)    asm("mul.rn.f32x2 %0, %1, %2;"     : "=l"(d) : "l"(a), "l"(b))
#define SPLAT2(d, s)     asm("mov.b64 %0, {%1, %1};"        : "=l"(d) : "r"(s))

__device__ __forceinline__ ull ld2s(const float* p) { return *(const ull*)p; }
__device__ __forceinline__ ull ld2g(const float* p) { return __ldg((const ull*)p); }
__device__ __forceinline__ float2 unp(ull v) { float2 f; memcpy(&f, &v, 8); return f; }

// ------------------------- host tables -------------------------------------
namespace tab {
static int nent = 0, ngrp = 0;
static uint2 h_ent[MAXE];
static uint2 h_grp[MAXG];
static int h_sliceStart[NSLICE + 1];
static unsigned h_dd0Item[16], h_dd1Item[24];
static int h_dd0Start[NSLICE + 1], h_dd1Start[NSLICE + 1];
static bool built = false;

static double lf(int n) { return lgamma((double)n + 1.0); }

static double cgc(int l1, int m1, int l2, int m2, int l3, int m3) {
    if (m1 + m2 != m3 || l3 < abs(l1 - l2) || l3 > l1 + l2) return 0.0;
    double pre = 0.5 * (lf(l1+l2-l3) + lf(l1-l2+l3) + lf(-l1+l2+l3) - lf(l1+l2+l3+1)
                 + lf(l1+m1) + lf(l1-m1) + lf(l2+m2) + lf(l2-m2) + lf(l3+m3) + lf(l3-m3));
    int kmin = std::max(0, std::max(l2-l3-m1, l1-l3+m2));
    int kmax = std::min(l1+l2-l3, std::min(l1-m1, l2+m2));
    double s = 0.0;
    for (int k = kmin; k <= kmax; k++) {
        double ln = lf(k) + lf(l1+l2-l3-k) + lf(l1-m1-k) + lf(l2+m2-k)
                  + lf(l3-l2+m1+k) + lf(l3-l1-m2+k);
        s += ((k & 1) ? -1.0 : 1.0) * exp(pre - ln);
    }
    return sqrt(2.0*l3+1.0) * s;
}

static int degof(int lm){ return lm>=16?4: lm>=9?3: lm>=4?2: lm>=1?1:0; }

struct Rent { int path, ic, ia, ib; double v; };
static std::complex<double> Cc[25][25][25];

static void build() {
    if (built) return;
    built = true;
    int pid[5][5][5];
    for (int a=0;a<5;a++)for(int b=0;b<5;b++)for(int c=0;c<5;c++) pid[a][b][c]=-1;
    int np = 0;
    for (int l1=0;l1<=4;l1++)
        for (int l2=0;l2<=4;l2++)
            for (int l3=abs(l1-l2); l3<=std::min(4,l1+l2); l3++)
                pid[l1][l2][l3] = np++;

    for (int l1=0;l1<=4;l1++)
        for (int l2=0;l2<=4;l2++)
            for (int l3=abs(l1-l2); l3<=std::min(4,l1+l2); l3++)
                for (int m1=-l1;m1<=l1;m1++)
                    for (int m2=-l2;m2<=l2;m2++) {
                        int m3 = m1+m2;
                        if (abs(m3) <= l3)
                            Cc[l1*l1+l1+m1][l2*l2+l2+m2][l3*l3+l3+m3] = cgc(l1,m1,l2,m2,l3,m3);
                    }

    const double s2 = 1.0/sqrt(2.0);
    std::complex<double> Uv[25][2]; int Uc[25][2]; int Un[25];
    for (int l=0;l<=4;l++) {
        int off = l*l+l;
        Un[off]=1; Uc[off][0]=off; Uv[off][0]={1,0}; Uc[off][1]=off; Uv[off][1]={0,0};
        for (int m=1;m<=l;m++) {
            double sg = (m&1)?-1.0:1.0;
            Un[off+m]=2;
            Uc[off+m][0]=off+m; Uv[off+m][0]={sg*s2,0};
            Uc[off+m][1]=off-m; Uv[off+m][1]={s2,0};
            Un[off-m]=2;
            Uc[off-m][0]=off-m; Uv[off-m][0]={0,s2};
            Uc[off-m][1]=off+m; Uv[off-m][1]={0,-sg*s2};
        }
    }

    std::vector<Rent> es; es.reserve(5000);
    for (int i=0;i<25;i++)
        for (int j=0;j<25;j++)
            for (int k=0;k<25;k++) {
                std::complex<double> T(0,0);
                for (int a=0;a<Un[i];a++)
                    for (int b=0;b<Un[j];b++)
                        for (int c=0;c<Un[k];c++)
                            T += Uv[i][a]*Uv[j][b]*std::conj(Uv[k][c])*Cc[Uc[i][a]][Uc[j][b]][Uc[k][c]];
                double C = T.real() + T.imag();
                if (std::fabs(C) < 1e-12) continue;
                int p = pid[degof(i)][degof(j)][degof(k)];
                if (p < 0) continue;
                es.push_back({p, k, i, j, C});
            }

    std::sort(es.begin(), es.end(), [](const Rent&a, const Rent&b){
        if (a.path!=b.path) return a.path<b.path;
        if (a.ic!=b.ic) return a.ic<b.ic;
        if (a.ia!=b.ia) return a.ia<b.ia;
        return a.ib<b.ib; });

    nent = (int)std::min((size_t)MAXE, es.size());

    // entries packed; "reload-a" flag on bit 15 (runs of equal ia within group)
    std::vector<int> gstart, gcnt, gic, gss, gpath;
    int lastp=-1, lastic=-1, lastia=-1;
    for (int e=0;e<nent;e++) {
        bool newgrp = (es[e].path!=lastp || es[e].ic!=lastic);
        if (newgrp) {
            lastp = es[e].path; lastic = es[e].ic; lastia = -1;
            gstart.push_back(e); gcnt.push_back(0);
            gic.push_back(es[e].ic);
            gss.push_back((degof(es[e].ia)+degof(es[e].ib)+degof(es[e].ic))&1);
            gpath.push_back(es[e].path);
        }
        gcnt.back()++;
        unsigned iao = (unsigned)(es[e].ia*128);
        if (es[e].ia != lastia) { iao |= 0x8000u; lastia = es[e].ia; }
        h_ent[e].x = iao | ((unsigned)(es[e].ib*128)<<16);
        float vv = (float)es[e].v;
        unsigned vb; memcpy(&vb, &vv, 4);
        h_ent[e].y = vb;
    }
    int NG = (int)gstart.size();

    // ---- ic-ownership: assign each ic (0..24) to one warp, greedy by load ----
    {
        long icLoad[25] = {0};
        for (int g=0; g<NG; g++) icLoad[gic[g]] += gcnt[g] + 3;
        int icOrd[25];
        for (int i=0;i<25;i++) icOrd[i]=i;
        std::sort(icOrd, icOrd+25, [&](int a, int b){ return icLoad[a]>icLoad[b]; });
        int icWarp[25];
        long load[NSLICE] = {0};
        for (int oi=0; oi<25; oi++) {
            int ic = icOrd[oi];
            int m = 0;
            for (int k=1;k<NSLICE;k++) if (load[k]<load[m]) m=k;
            icWarp[ic]=m; load[m]+=icLoad[ic];
        }
        // emit groups warp-by-warp, ic runs contiguous, flush flag on last of run
        int pos=0;
        for (int s=0;s<NSLICE;s++) {
            h_sliceStart[s]=pos;
            for (int ic=0; ic<25; ic++) {
                if (icWarp[ic]!=s) continue;
                int lastPos = -1;
                for (int g=0; g<NG && pos<MAXG; g++) {
                    if (gic[g]!=ic) continue;
                    h_grp[pos].x = (unsigned)gstart[g] | ((unsigned)gcnt[g]<<16);
                    h_grp[pos].y = (unsigned)ic | ((unsigned)gss[g]<<5)
                                 | ((unsigned)gpath[g]<<8);
                    lastPos = pos;
                    pos++;
                }
                if (lastPos >= 0) h_grp[lastPos].y |= (1u<<6);   // flush
            }
        }
        h_sliceStart[NSLICE]=pos; ngrp=pos;
    }

    // dd items: enc = L | p<<3 | q0<<4 | qn<<8 ; rows chunked to <=5
    struct It { unsigned enc; int cost; };
    auto pack=[](int p,int L,int q0,int qn){
        return (unsigned)L | ((unsigned)p<<3) | ((unsigned)q0<<4) | ((unsigned)qn<<8);
    };
    auto greedy=[&](std::vector<It>& v, unsigned* items, int* starts){
        std::sort(v.begin(), v.end(), [](const It&a, const It&b){ return a.cost>b.cost; });
        long load[NSLICE]={0};
        std::vector<int> asg(v.size());
        for (size_t i=0;i<v.size();i++) {
            int m=0;
            for (int k=1;k<NSLICE;k++) if (load[k]<load[m]) m=k;
            asg[i]=m; load[m]+=v[i].cost;
        }
        int pos=0;
        for (int s=0;s<NSLICE;s++) {
            starts[s]=pos;
            for (size_t i=0;i<v.size();i++) if (asg[i]==s) items[pos++]=v[i].enc;
        }
        starts[NSLICE]=pos;
    };
    {
        std::vector<It> v1;
        for (int p=0;p<2;p++)
            for (int L=0;L<5;L++) {
                int NL = 2*L+1;
                for (int q0=0; q0<NL; q0+=5) {
                    int qn = std::min(5, NL-q0);
                    v1.push_back({pack(p,L,q0,qn), qn*64});
                }
            }
        greedy(v1, h_dd1Item, h_dd1Start);
        std::vector<It> v0;
        for (int L=0;L<5;L++) {
            int NL = 2*L+1;
            for (int q0=0; q0<NL; q0+=5) {
                int qn = std::min(5, NL-q0);
                v0.push_back({pack(0,L,q0,qn), qn*16});
            }
        }
        greedy(v0, h_dd0Item, h_dd0Start);
    }
}
} // namespace tab

// ------------------------- wp repack kernel ---------------------------------
// t1wp [65][4 pair][64 ch] -> g_wpPack [65][32 ch2][8: w00x w00y w01x w01y w10x w10y w11x w11y]
__global__ void repack_wp(const float* __restrict__ wp) {
    int t = blockIdx.x * 256 + threadIdx.x;
    if (t < 65 * 256) {
        int path = t >> 8, r = t & 255;
        int ch2 = r >> 3, j = r & 7;
        int pair = j >> 1, comp = j & 1;
        g_wpPack[t] = __ldg(wp + path*256 + pair*64 + ch2*2 + comp);
    }
}

// ------------------------- edge kernel --------------------------------------
__global__ __launch_bounds__(256) void edge_kernel(
    const int* __restrict__ an, const int* __restrict__ nbr,
    const float* __restrict__ disp, const float* __restrict__ Wsp,
    const float* __restrict__ norm, int E)
{
    __shared__ float sYe[8][32];
    __shared__ float sG[8][16];
    int w = threadIdx.x >> 5, lane = threadIdx.x & 31;
    int e = blockIdx.x*8 + w;
    if (e >= E) return;

    int i = __ldg(nbr + 2*e), j = __ldg(nbr + 2*e + 1);
    float dx = __ldg(disp+3*e), dy = __ldg(disp+3*e+1), dz = __ldg(disp+3*e+2);
    float r = sqrtf(dx*dx + dy*dy + dz*dz + 1e-12f);
    float inv = 1.0f/r;
    float x = dx*inv, y = dy*inv, z = dz*inv;

    float t = fminf(r*0.2f, 1.0f);
    float fc = 0.5f*(cosf(3.14159265358979f*t) + 1.0f);
    float rb = 0.0f;
    if (lane < 16) {
        float d = r - (float)lane*(1.0f/3.0f);
        rb = __expf(-10.24f*d*d)*fc;
    }

    int Z = __ldg(an + j);
    const float* Wr = Wsp + (size_t)Z*256;
    float g = 0.0f;
    #pragma unroll
    for (int k=0;k<16;k++) {
        float rk = __shfl_sync(0xffffffffu, rb, k);
        float wv = (lane<16) ? __ldg(Wr + k*16 + lane) : 0.0f;
        g = fmaf(rk, wv, g);
    }
    if (lane < 16) sG[w][lane] = g / __ldg(norm);

    float x2=x*x, y2=y*y, z2=z*z;
    if (lane == 0) {
        float* S = sYe[w];
        S[0]=0.28209479177387814f;
        S[1]=0.4886025119029199f*y;  S[2]=0.4886025119029199f*z;  S[3]=0.4886025119029199f*x;
        S[4]=1.0925484305920792f*x*y; S[5]=1.0925484305920792f*y*z;
        S[6]=0.31539156525252005f*(3.f*z2-1.f);
        S[7]=1.0925484305920792f*x*z; S[8]=0.5462742152960396f*(x2-y2);
        S[9]=0.5900435899266435f*y*(3.f*x2-y2);
        S[10]=2.890611442640554f*x*y*z;
        S[11]=0.4570457994644658f*y*(5.f*z2-1.f);
        S[12]=0.3731763325901154f*z*(5.f*z2-3.f);
        S[13]=0.4570457994644658f*x*(5.f*z2-1.f);
        S[14]=1.445305721320277f*z*(x2-y2);
        S[15]=0.5900435899266435f*x*(x2-3.f*y2);
        S[16]=2.5033429417967046f*x*y*(x2-y2);
        S[17]=1.7701307697799304f*y*z*(3.f*x2-y2);
        S[18]=0.9461746957575601f*x*y*(7.f*z2-1.f);
        S[19]=0.6690465435572892f*y*z*(7.f*z2-3.f);
        S[20]=0.10578554691520431f*(35.f*z2*z2-30.f*z2+3.f);
        S[21]=0.6690465435572892f*x*z*(7.f*z2-3.f);
        S[22]=0.47308734787878004f*(x2-y2)*(7.f*z2-1.f);
        S[23]=1.7701307697799304f*x*z*(x2-3.f*y2);
        S[24]=0.6258357354491761f*(x2*x2-6.f*x2*y2+y2*y2);
    }
    __syncwarp();

    size_t base = (size_t)i*400;
    #pragma unroll
    for (int it=0; it<13; it++) {
        int tt = lane + it*32;
        if (tt < 400)
            atomicAdd(&g_Y0[base + tt], sYe[w][tt>>4] * sG[w][tt&15]);
    }
}

// ------------------------- dd block -----------------------------------------
template<int YS>
__device__ __forceinline__ void dd_block(const float* __restrict__ yrow,
    float* oA, float* oB,
    const float* __restrict__ W1, const float* __restrict__ W2,
    int qn, int fc)
{
    ull aA[5], aB[5];
    #pragma unroll
    for (int q=0;q<5;q++){ aA[q]=0ull; aB[q]=0ull; }
    for (int f=0; f<fc; f+=2) {
        ull w1a = ld2g(W1 + f*64);
        ull w1b = ld2g(W1 + f*64 + 64);
        ull w2a = ld2g(W2 + f*64);
        ull w2b = ld2g(W2 + f*64 + 64);
        #pragma unroll
        for (int q=0;q<5;q++) {
            if (q < qn) {
                ull yp = ld2s(yrow + q*YS + f);
                unsigned ylo, yhi;
                asm("mov.b64 {%0,%1}, %2;" : "=r"(ylo), "=r"(yhi) : "l"(yp));
                ull ys0, ys1; SPLAT2(ys0, ylo); SPLAT2(ys1, yhi);
                FMA2(aA[q], ys0, w1a, aA[q]);
                FMA2(aA[q], ys1, w1b, aA[q]);
                FMA2(aB[q], ys0, w2a, aB[q]);
                FMA2(aB[q], ys1, w2b, aB[q]);
            }
        }
    }
    #pragma unroll
    for (int q=0;q<5;q++) {
        if (q < qn) {
            *(ull*)(oA + q*128) = aA[q];
            *(ull*)(oB + q*128) = aB[q];
        }
    }
}

// ------------------------- atom kernel --------------------------------------
// smem (floats): sy0[25][16]; sa/sb packed [25][32ch2][4]; sy1/sy2 [25][2][64]
__global__ __launch_bounds__(256, 4) void atom_kernel(
    const int* __restrict__ an,
    const float* __restrict__ emb, const float* __restrict__ W_et,
    const float* __restrict__ b_et,
    const float* __restrict__ t0W1, const float* __restrict__ t0W2,
    const float* __restrict__ t0wp,
    const float* __restrict__ t1W1, const float* __restrict__ t1W2,
    const float* __restrict__ wfu, float* __restrict__ out, int N)
{
    extern __shared__ float sm[];
    float* sy0  = sm;           // 400
    float* sa   = sm + 400;     // 3200
    float* sb   = sa + 3200;    // 3200
    float* sy1  = sb + 3200;    // 3200
    float* sy2  = sy1 + 3200;   // 3200
    float* ste  = sy2 + 3200;   // 144
    float* semb = ste + 144;    // 64

    int n = blockIdx.x;
    if (n >= N) return;
    int tid = threadIdx.x;
    int w = tid >> 5, lane = tid & 31;
    int lane2 = lane * 2;
    int lane4 = lane * 4;

    // ---- P1: loads (no zeroing needed — every slot is overwritten) ----
    for (int t = tid; t < 400; t += 256) sy0[t] = g_Y0[(size_t)n*400 + t];
    if (tid < 64) {
        int Z = __ldg(an + n);
        semb[tid] = __ldg(emb + (size_t)Z*64 + tid);
    }
    __syncthreads();

    // ---- P2: dd0 (exclusive row chunks, parity0, fc=16) + te ----
    for (int it = c_dd0Start[w]; it < c_dd0Start[w+1]; it++) {
        unsigned I = c_dd0Item[it];
        int L = I & 7, q0 = (I>>4)&15, qn = (I>>8)&15;
        int lm0 = L*L + q0;
        dd_block<16>(sy0 + lm0*16,
                     sa + lm0*128 + lane4, sb + lm0*128 + lane4,
                     t0W1 + L*1024 + lane2, t0W2 + L*1024 + lane2,
                     qn, 16);
    }
    if (tid < 144) {
        float acc = __ldg(b_et + tid);
        #pragma unroll 8
        for (int d = 0; d < 64; d++)
            acc = fmaf(semb[d], __ldg(W_et + d*144 + tid), acc);
        ste[tid] = acc;
    }
    __syncthreads();

    // ---- P3: tp0 (parity0 only; register acc across groups of one ic) ----
    {
        int g0 = c_sliceStart[w], g1 = c_sliceStart[w+1];
        const float* Abase = sa + lane4;
        const float* Bbase = sb + lane4;
        float p0x = 0.f, p0y = 0.f, p1x = 0.f, p1y = 0.f;
        for (int gi = g0; gi < g1; gi++) {
            uint2 G = __ldg(&g_grp[gi]);
            int start = G.x & 0xFFFF, cnt = (int)(G.x >> 16);
            int ic = G.y & 31, s = (G.y>>5)&1, fl = (G.y>>6)&1, path = (int)(G.y>>8);
            ull s00 = 0, a0 = 0;
            for (int k = 0; k < cnt; k++) {
                uint2 Ee = __ldg(&g_ent[start+k]);
                unsigned xi = Ee.x;
                if (xi & 0x8000u)
                    a0 = ld2s(Abase + (xi & 0x7FFFu));
                ull b0 = ld2s(Bbase + (xi >> 16));
                ull vv; SPLAT2(vv, Ee.y);
                ull p00; MUL2(p00, a0, b0);
                FMA2(s00, vv, p00, s00);
            }
            float2 t00 = unp(s00);
            float2 w00 = *(const float2*)(t0wp + path*256 + lane2);
            float ex = w00.x * t00.x, ey = w00.y * t00.y;
            if (s == 0) { p0x += ex; p0y += ey; }
            else        { p1x += ex; p1y += ey; }
            if (fl) {
                *(float2*)(sy1 + ic*128 + lane2)      = make_float2(p0x, p0y);
                *(float2*)(sy1 + ic*128 + 64 + lane2) = make_float2(p1x, p1y);
                p0x = p0y = p1x = p1y = 0.f;
            }
        }
    }
    __syncthreads();

    // ---- P4: dd1 (exclusive row chunks, both parities, fc=64) ----
    for (int it = c_dd1Start[w]; it < c_dd1Start[w+1]; it++) {
        unsigned I = c_dd1Item[it];
        int L = I & 7, p = (I>>3)&1, q0 = (I>>4)&15, qn = (I>>8)&15;
        int lm0 = L*L + q0;
        dd_block<128>(sy1 + lm0*128 + p*64,
                      sa + lm0*128 + lane4 + 2*p, sb + lm0*128 + lane4 + 2*p,
                      t1W1 + p*20480 + L*4096 + lane2,
                      t1W2 + p*20480 + L*4096 + lane2,
                      qn, 64);
    }
    __syncthreads();

    // ---- P5: tp1 (both parities; register acc per ic; packed wp loads) ----
    {
        int g0 = c_sliceStart[w], g1 = c_sliceStart[w+1];
        const float* Abase = sa + lane4;
        const float* Bbase = sb + lane4;
        float p0x = 0.f, p0y = 0.f, p1x = 0.f, p1y = 0.f;
        for (int gi = g0; gi < g1; gi++) {
            uint2 G = __ldg(&g_grp[gi]);
            int start = G.x & 0xFFFF, cnt = (int)(G.x >> 16);
            int ic = G.y & 31, s = (G.y>>5)&1, fl = (G.y>>6)&1, path = (int)(G.y>>8);
            ull s00 = 0, s11 = 0, s01 = 0, s10 = 0;
            ull a0 = 0, a1 = 0;
            for (int k = 0; k < cnt; k++) {
                uint2 Ee = __ldg(&g_ent[start+k]);
                unsigned xi = Ee.x;
                if (xi & 0x8000u) {
                    ulonglong2 av = *(const ulonglong2*)(Abase + (xi & 0x7FFFu));
                    a0 = av.x; a1 = av.y;
                }
                ulonglong2 bv = *(const ulonglong2*)(Bbase + (xi >> 16));
                ull b0 = bv.x, b1 = bv.y;
                ull vv; SPLAT2(vv, Ee.y);
                ull p00, p11, p01, p10;
                MUL2(p00, a0, b0); MUL2(p11, a1, b1);
                MUL2(p01, a0, b1); MUL2(p10, a1, b0);
                FMA2(s00, vv, p00, s00);
                FMA2(s11, vv, p11, s11);
                FMA2(s01, vv, p01, s01);
                FMA2(s10, vv, p10, s10);
            }
            const float4* wp4 = (const float4*)(g_wpPack + path*256 + lane*8);
            float4 wA = __ldg(wp4);       // w00x w00y w01x w01y
            float4 wB = __ldg(wp4 + 1);   // w10x w10y w11x w11y
            float2 t00 = unp(s00), t11 = unp(s11), t01 = unp(s01), t10 = unp(s10);
            float evx = fmaf(wA.x, t00.x, wB.z * t11.x);
            float evy = fmaf(wA.y, t00.y, wB.w * t11.y);
            float odx = fmaf(wA.z, t01.x, wB.x * t10.x);
            float ody = fmaf(wA.w, t01.y, wB.y * t10.y);
            if (s == 0) { p0x += evx; p0y += evy; p1x += odx; p1y += ody; }
            else        { p0x += odx; p0y += ody; p1x += evx; p1y += evy; }
            if (fl) {
                *(float2*)(sy2 + ic*128 + lane2)      = make_float2(p0x, p0y);
                *(float2*)(sy2 + ic*128 + 64 + lane2) = make_float2(p1x, p1y);
                p0x = p0y = p1x = p1y = 0.f;
            }
        }
    }
    __syncthreads();

    // ---- P6: fused epilogue + mish ----
    for (int t = tid; t < 7200; t += 256) {
        int p = t/3600, rem = t - p*3600;
        int lm = rem/144, c = rem - lm*144;
        float feat;
        if (c < 16)       feat = p ? 0.f : sy0[lm*16 + c];
        else if (c < 80)  feat = sy1[lm*128 + p*64 + (c-16)];
        else              feat = sy2[lm*128 + p*64 + (c-80)];
        int dg = lm>=16?4: lm>=9?3: lm>=4?2: lm>=1?1:0;
        float v = ste[c] * feat * __ldg(wfu + p*720 + dg*144 + c);
        if (p==0 && lm==0) v += ste[c];
        float ev = __expf(v);
        float w1v = 1.f + ev;
        float wv  = w1v*w1v;
        float rr  = (v > 20.f) ? 2.f*v : v * __fdividef(2.f*wv, wv + 1.f);
        out[(size_t)n*7200 + t] = rr;
    }
}

// ------------------------- launch ------------------------------------------
extern "C" void kernel_launch(void* const* d_in, const int* in_sizes, int n_in,
                              void* d_out, int out_size)
{
    tab::build();

    const int*   an   = (const int*)d_in[0];
    const int*   nbr  = (const int*)d_in[1];
    const float* disp = (const float*)d_in[2];
    const float* Wsp  = (const float*)d_in[3];
    const float* emb  = (const float*)d_in[4];
    const float* W_et = (const float*)d_in[5];
    const float* b_et = (const float*)d_in[6];
    const float* norm = (const float*)d_in[7];
    const float* t0W1 = (const float*)d_in[8];
    const float* t0W2 = (const float*)d_in[9];
    const float* t0wp = (const float*)d_in[10];
    const float* t1W1 = (const float*)d_in[11];
    const float* t1W2 = (const float*)d_in[12];
    const float* t1wp = (const float*)d_in[13];
    const float* wfu  = (const float*)d_in[14];
    float* out = (float*)d_out;

    int N = in_sizes[0];
    int E = in_sizes[1] / 2;

    cudaMemcpyToSymbolAsync(g_ent, tab::h_ent, tab::nent*sizeof(uint2),
                            0, cudaMemcpyHostToDevice, 0);
    cudaMemcpyToSymbolAsync(g_grp, tab::h_grp, tab::ngrp*sizeof(uint2),
                            0, cudaMemcpyHostToDevice, 0);
    cudaMemcpyToSymbolAsync(c_sliceStart, tab::h_sliceStart, (NSLICE+1)*sizeof(int),
                            0, cudaMemcpyHostToDevice, 0);
    cudaMemcpyToSymbolAsync(c_dd0Start, tab::h_dd0Start, (NSLICE+1)*sizeof(int),
                            0, cudaMemcpyHostToDevice, 0);
    cudaMemcpyToSymbolAsync(c_dd1Start, tab::h_dd1Start, (NSLICE+1)*sizeof(int),
                            0, cudaMemcpyHostToDevice, 0);
    cudaMemcpyToSymbolAsync(c_dd0Item, tab::h_dd0Item, sizeof(tab::h_dd0Item),
                            0, cudaMemcpyHostToDevice, 0);
    cudaMemcpyToSymbolAsync(c_dd1Item, tab::h_dd1Item, sizeof(tab::h_dd1Item),
                            0, cudaMemcpyHostToDevice, 0);

    void* y0ptr = nullptr;
    cudaGetSymbolAddress(&y0ptr, g_Y0);
    cudaMemsetAsync(y0ptr, 0, (size_t)N*400*sizeof(float), 0);

    repack_wp<<<65, 256>>>(t1wp);
    edge_kernel<<<(E + 7)/8, 256>>>(an, nbr, disp, Wsp, norm, E);

    static bool attr_done = false;
    size_t smem = 13408 * sizeof(float);
    if (!attr_done) {
        cudaFuncSetAttribute(atom_kernel, cudaFuncAttributeMaxDynamicSharedMemorySize,
                             (int)smem);
        attr_done = true;
    }
    atom_kernel<<<N, 256, smem>>>(an, emb, W_et, b_et, t0W1, t0W2, t0wp,
                                  t1W1, t1W2, wfu, out, N);
}

// round 14
// speedup vs baseline: 1.1965x; 1.0621x over previous
#include <cuda_runtime.h>
#include <cmath>
#include <cstdint>
#include <cstring>
#include <complex>
#include <vector>
#include <algorithm>

#define MAXE 7000
#define MAXG 600
#define MAXN 10000
#define NSLICE 8

static __device__ float g_Y0[(size_t)MAXN * 400];
static __device__ uint2 g_ent[MAXE];
static __device__ uint2 g_grp[MAXG];
static __device__ float g_wpPack[65 * 256];
__constant__ int c_sliceStart[NSLICE + 1];
__constant__ int c_dd0Start[NSLICE + 1];
__constant__ int c_dd1Start[NSLICE + 1];
__constant__ unsigned c_dd0Item[16];
__constant__ unsigned c_dd1Item[24];

typedef unsigned long long ull;

#define FMA2(d, a, b, c) asm("fma.rn.f32x2 %0, %1, %2, %3;" : "=l"(d) : "l"(a), "l"(b), "l"(c))
#define MUL2(d, a, b)    asm("mul.rn.f32x2 %0, %1, %2;"     : "=l"(d) : "l"(a), "l"(b))
#define SPLAT2(d, s)     asm("mov.b64 %0, {%1, %1};"        : "=l"(d) : "r"(s))

__device__ __forceinline__ ull ld2s(const float* p) { return *(const ull*)p; }
__device__ __forceinline__ ull ld2g(const float* p) { return __ldg((const ull*)p); }
__device__ __forceinline__ float2 unp(ull v) { float2 f; memcpy(&f, &v, 8); return f; }

__device__ __forceinline__ float mish(float v) {
    float ev = __expf(v);
    float w1 = 1.f + ev;
    float w  = w1 * w1;
    return (v > 20.f) ? 2.f * v : v * __fdividef(2.f * w, w + 1.f);
}

// ------------------------- host tables -------------------------------------
namespace tab {
static int nent = 0, ngrp = 0;
static uint2 h_ent[MAXE];
static uint2 h_grp[MAXG];
static int h_sliceStart[NSLICE + 1];
static unsigned h_dd0Item[16], h_dd1Item[24];
static int h_dd0Start[NSLICE + 1], h_dd1Start[NSLICE + 1];
static bool built = false;

static double lf(int n) { return lgamma((double)n + 1.0); }

static double cgc(int l1, int m1, int l2, int m2, int l3, int m3) {
    if (m1 + m2 != m3 || l3 < abs(l1 - l2) || l3 > l1 + l2) return 0.0;
    double pre = 0.5 * (lf(l1+l2-l3) + lf(l1-l2+l3) + lf(-l1+l2+l3) - lf(l1+l2+l3+1)
                 + lf(l1+m1) + lf(l1-m1) + lf(l2+m2) + lf(l2-m2) + lf(l3+m3) + lf(l3-m3));
    int kmin = std::max(0, std::max(l2-l3-m1, l1-l3+m2));
    int kmax = std::min(l1+l2-l3, std::min(l1-m1, l2+m2));
    double s = 0.0;
    for (int k = kmin; k <= kmax; k++) {
        double ln = lf(k) + lf(l1+l2-l3-k) + lf(l1-m1-k) + lf(l2+m2-k)
                  + lf(l3-l2+m1+k) + lf(l3-l1-m2+k);
        s += ((k & 1) ? -1.0 : 1.0) * exp(pre - ln);
    }
    return sqrt(2.0*l3+1.0) * s;
}

static int degof(int lm){ return lm>=16?4: lm>=9?3: lm>=4?2: lm>=1?1:0; }

struct Rent { int path, ic, ia, ib; double v; };
static std::complex<double> Cc[25][25][25];

static void build() {
    if (built) return;
    built = true;
    int pid[5][5][5];
    for (int a=0;a<5;a++)for(int b=0;b<5;b++)for(int c=0;c<5;c++) pid[a][b][c]=-1;
    int np = 0;
    for (int l1=0;l1<=4;l1++)
        for (int l2=0;l2<=4;l2++)
            for (int l3=abs(l1-l2); l3<=std::min(4,l1+l2); l3++)
                pid[l1][l2][l3] = np++;

    for (int l1=0;l1<=4;l1++)
        for (int l2=0;l2<=4;l2++)
            for (int l3=abs(l1-l2); l3<=std::min(4,l1+l2); l3++)
                for (int m1=-l1;m1<=l1;m1++)
                    for (int m2=-l2;m2<=l2;m2++) {
                        int m3 = m1+m2;
                        if (abs(m3) <= l3)
                            Cc[l1*l1+l1+m1][l2*l2+l2+m2][l3*l3+l3+m3] = cgc(l1,m1,l2,m2,l3,m3);
                    }

    const double s2 = 1.0/sqrt(2.0);
    std::complex<double> Uv[25][2]; int Uc[25][2]; int Un[25];
    for (int l=0;l<=4;l++) {
        int off = l*l+l;
        Un[off]=1; Uc[off][0]=off; Uv[off][0]={1,0}; Uc[off][1]=off; Uv[off][1]={0,0};
        for (int m=1;m<=l;m++) {
            double sg = (m&1)?-1.0:1.0;
            Un[off+m]=2;
            Uc[off+m][0]=off+m; Uv[off+m][0]={sg*s2,0};
            Uc[off+m][1]=off-m; Uv[off+m][1]={s2,0};
            Un[off-m]=2;
            Uc[off-m][0]=off-m; Uv[off-m][0]={0,s2};
            Uc[off-m][1]=off+m; Uv[off-m][1]={0,-sg*s2};
        }
    }

    std::vector<Rent> es; es.reserve(5000);
    for (int i=0;i<25;i++)
        for (int j=0;j<25;j++)
            for (int k=0;k<25;k++) {
                std::complex<double> T(0,0);
                for (int a=0;a<Un[i];a++)
                    for (int b=0;b<Un[j];b++)
                        for (int c=0;c<Un[k];c++)
                            T += Uv[i][a]*Uv[j][b]*std::conj(Uv[k][c])*Cc[Uc[i][a]][Uc[j][b]][Uc[k][c]];
                double C = T.real() + T.imag();
                if (std::fabs(C) < 1e-12) continue;
                int p = pid[degof(i)][degof(j)][degof(k)];
                if (p < 0) continue;
                es.push_back({p, k, i, j, C});
            }

    std::sort(es.begin(), es.end(), [](const Rent&a, const Rent&b){
        if (a.path!=b.path) return a.path<b.path;
        if (a.ic!=b.ic) return a.ic<b.ic;
        if (a.ia!=b.ia) return a.ia<b.ia;
        return a.ib<b.ib; });

    nent = (int)std::min((size_t)MAXE, es.size());

    std::vector<int> gstart, gcnt, gic, gss, gpath;
    int lastp=-1, lastic=-1, lastia=-1;
    for (int e=0;e<nent;e++) {
        bool newgrp = (es[e].path!=lastp || es[e].ic!=lastic);
        if (newgrp) {
            lastp = es[e].path; lastic = es[e].ic; lastia = -1;
            gstart.push_back(e); gcnt.push_back(0);
            gic.push_back(es[e].ic);
            gss.push_back((degof(es[e].ia)+degof(es[e].ib)+degof(es[e].ic))&1);
            gpath.push_back(es[e].path);
        }
        gcnt.back()++;
        unsigned iao = (unsigned)(es[e].ia*128);
        if (es[e].ia != lastia) { iao |= 0x8000u; lastia = es[e].ia; }
        h_ent[e].x = iao | ((unsigned)(es[e].ib*128)<<16);
        float vv = (float)es[e].v;
        unsigned vb; memcpy(&vb, &vv, 4);
        h_ent[e].y = vb;
    }
    int NG = (int)gstart.size();

    // ic-ownership: assign each ic to one warp (greedy by load)
    {
        long icLoad[25] = {0};
        for (int g=0; g<NG; g++) icLoad[gic[g]] += gcnt[g] + 3;
        int icOrd[25];
        for (int i=0;i<25;i++) icOrd[i]=i;
        std::sort(icOrd, icOrd+25, [&](int a, int b){ return icLoad[a]>icLoad[b]; });
        int icWarp[25];
        long load[NSLICE] = {0};
        for (int oi=0; oi<25; oi++) {
            int ic = icOrd[oi];
            int m = 0;
            for (int k=1;k<NSLICE;k++) if (load[k]<load[m]) m=k;
            icWarp[ic]=m; load[m]+=icLoad[ic];
        }
        int pos=0;
        for (int s=0;s<NSLICE;s++) {
            h_sliceStart[s]=pos;
            for (int ic=0; ic<25; ic++) {
                if (icWarp[ic]!=s) continue;
                int lastPos = -1;
                for (int g=0; g<NG && pos<MAXG; g++) {
                    if (gic[g]!=ic) continue;
                    h_grp[pos].x = (unsigned)gstart[g] | ((unsigned)gcnt[g]<<16);
                    h_grp[pos].y = (unsigned)ic | ((unsigned)gss[g]<<5)
                                 | ((unsigned)gpath[g]<<8);
                    lastPos = pos;
                    pos++;
                }
                if (lastPos >= 0) h_grp[lastPos].y |= (1u<<6);   // flush
            }
        }
        h_sliceStart[NSLICE]=pos; ngrp=pos;
    }

    // dd items
    struct It { unsigned enc; int cost; };
    auto pack=[](int p,int L,int q0,int qn){
        return (unsigned)L | ((unsigned)p<<3) | ((unsigned)q0<<4) | ((unsigned)qn<<8);
    };
    auto greedy=[&](std::vector<It>& v, unsigned* items, int* starts){
        std::sort(v.begin(), v.end(), [](const It&a, const It&b){ return a.cost>b.cost; });
        long load[NSLICE]={0};
        std::vector<int> asg(v.size());
        for (size_t i=0;i<v.size();i++) {
            int m=0;
            for (int k=1;k<NSLICE;k++) if (load[k]<load[m]) m=k;
            asg[i]=m; load[m]+=v[i].cost;
        }
        int pos=0;
        for (int s=0;s<NSLICE;s++) {
            starts[s]=pos;
            for (size_t i=0;i<v.size();i++) if (asg[i]==s) items[pos++]=v[i].enc;
        }
        starts[NSLICE]=pos;
    };
    {
        std::vector<It> v1;
        for (int p=0;p<2;p++)
            for (int L=0;L<5;L++) {
                int NL = 2*L+1;
                for (int q0=0; q0<NL; q0+=5) {
                    int qn = std::min(5, NL-q0);
                    v1.push_back({pack(p,L,q0,qn), qn*64});
                }
            }
        greedy(v1, h_dd1Item, h_dd1Start);
        std::vector<It> v0;
        for (int L=0;L<5;L++) {
            int NL = 2*L+1;
            for (int q0=0; q0<NL; q0+=5) {
                int qn = std::min(5, NL-q0);
                v0.push_back({pack(0,L,q0,qn), qn*16});
            }
        }
        greedy(v0, h_dd0Item, h_dd0Start);
    }
}
} // namespace tab

// ------------------------- wp repack kernel ---------------------------------
__global__ void repack_wp(const float* __restrict__ wp) {
    int t = blockIdx.x * 256 + threadIdx.x;
    if (t < 65 * 256) {
        int path = t >> 8, r = t & 255;
        int ch2 = r >> 3, j = r & 7;
        int pair = j >> 1, comp = j & 1;
        g_wpPack[t] = __ldg(wp + path*256 + pair*64 + ch2*2 + comp);
    }
}

// ------------------------- edge kernel --------------------------------------
__global__ __launch_bounds__(256) void edge_kernel(
    const int* __restrict__ an, const int* __restrict__ nbr,
    const float* __restrict__ disp, const float* __restrict__ Wsp,
    const float* __restrict__ norm, int E)
{
    __shared__ float sYe[8][32];
    __shared__ float sG[8][16];
    int w = threadIdx.x >> 5, lane = threadIdx.x & 31;
    int e = blockIdx.x*8 + w;
    if (e >= E) return;

    int i = __ldg(nbr + 2*e), j = __ldg(nbr + 2*e + 1);
    float dx = __ldg(disp+3*e), dy = __ldg(disp+3*e+1), dz = __ldg(disp+3*e+2);
    float r = sqrtf(dx*dx + dy*dy + dz*dz + 1e-12f);
    float inv = 1.0f/r;
    float x = dx*inv, y = dy*inv, z = dz*inv;

    float t = fminf(r*0.2f, 1.0f);
    float fc = 0.5f*(cosf(3.14159265358979f*t) + 1.0f);
    float rb = 0.0f;
    if (lane < 16) {
        float d = r - (float)lane*(1.0f/3.0f);
        rb = __expf(-10.24f*d*d)*fc;
    }

    int Z = __ldg(an + j);
    const float* Wr = Wsp + (size_t)Z*256;
    float g = 0.0f;
    #pragma unroll
    for (int k=0;k<16;k++) {
        float rk = __shfl_sync(0xffffffffu, rb, k);
        float wv = (lane<16) ? __ldg(Wr + k*16 + lane) : 0.0f;
        g = fmaf(rk, wv, g);
    }
    if (lane < 16) sG[w][lane] = g / __ldg(norm);

    float x2=x*x, y2=y*y, z2=z*z;
    if (lane == 0) {
        float* S = sYe[w];
        S[0]=0.28209479177387814f;
        S[1]=0.4886025119029199f*y;  S[2]=0.4886025119029199f*z;  S[3]=0.4886025119029199f*x;
        S[4]=1.0925484305920792f*x*y; S[5]=1.0925484305920792f*y*z;
        S[6]=0.31539156525252005f*(3.f*z2-1.f);
        S[7]=1.0925484305920792f*x*z; S[8]=0.5462742152960396f*(x2-y2);
        S[9]=0.5900435899266435f*y*(3.f*x2-y2);
        S[10]=2.890611442640554f*x*y*z;
        S[11]=0.4570457994644658f*y*(5.f*z2-1.f);
        S[12]=0.3731763325901154f*z*(5.f*z2-3.f);
        S[13]=0.4570457994644658f*x*(5.f*z2-1.f);
        S[14]=1.445305721320277f*z*(x2-y2);
        S[15]=0.5900435899266435f*x*(x2-3.f*y2);
        S[16]=2.5033429417967046f*x*y*(x2-y2);
        S[17]=1.7701307697799304f*y*z*(3.f*x2-y2);
        S[18]=0.9461746957575601f*x*y*(7.f*z2-1.f);
        S[19]=0.6690465435572892f*y*z*(7.f*z2-3.f);
        S[20]=0.10578554691520431f*(35.f*z2*z2-30.f*z2+3.f);
        S[21]=0.6690465435572892f*x*z*(7.f*z2-3.f);
        S[22]=0.47308734787878004f*(x2-y2)*(7.f*z2-1.f);
        S[23]=1.7701307697799304f*x*z*(x2-3.f*y2);
        S[24]=0.6258357354491761f*(x2*x2-6.f*x2*y2+y2*y2);
    }
    __syncwarp();

    size_t base = (size_t)i*400;
    #pragma unroll
    for (int it=0; it<13; it++) {
        int tt = lane + it*32;
        if (tt < 400)
            atomicAdd(&g_Y0[base + tt], sYe[w][tt>>4] * sG[w][tt&15]);
    }
}

// ------------------------- dd block -----------------------------------------
template<int YS>
__device__ __forceinline__ void dd_block(const float* __restrict__ yrow,
    float* oA, float* oB,
    const float* __restrict__ W1, const float* __restrict__ W2,
    int qn, int fc)
{
    ull aA[5], aB[5];
    #pragma unroll
    for (int q=0;q<5;q++){ aA[q]=0ull; aB[q]=0ull; }
    for (int f=0; f<fc; f+=2) {
        ull w1a = ld2g(W1 + f*64);
        ull w1b = ld2g(W1 + f*64 + 64);
        ull w2a = ld2g(W2 + f*64);
        ull w2b = ld2g(W2 + f*64 + 64);
        #pragma unroll
        for (int q=0;q<5;q++) {
            if (q < qn) {
                ull yp = ld2s(yrow + q*YS + f);
                unsigned ylo, yhi;
                asm("mov.b64 {%0,%1}, %2;" : "=r"(ylo), "=r"(yhi) : "l"(yp));
                ull ys0, ys1; SPLAT2(ys0, ylo); SPLAT2(ys1, yhi);
                FMA2(aA[q], ys0, w1a, aA[q]);
                FMA2(aA[q], ys1, w1b, aA[q]);
                FMA2(aB[q], ys0, w2a, aB[q]);
                FMA2(aB[q], ys1, w2b, aB[q]);
            }
        }
    }
    #pragma unroll
    for (int q=0;q<5;q++) {
        if (q < qn) {
            *(ull*)(oA + q*128) = aA[q];
            *(ull*)(oB + q*128) = aB[q];
        }
    }
}

// ------------------------- atom kernel --------------------------------------
// smem (floats): sy0[25][16]=400; sa/sb packed [25][32ch2][4]=3200 each;
//                sy1 [25][2][64]=3200; ste 144; semb 64. total 10208.
__global__ __launch_bounds__(256, 4) void atom_kernel(
    const int* __restrict__ an,
    const float* __restrict__ emb, const float* __restrict__ W_et,
    const float* __restrict__ b_et,
    const float* __restrict__ t0W1, const float* __restrict__ t0W2,
    const float* __restrict__ t0wp,
    const float* __restrict__ t1W1, const float* __restrict__ t1W2,
    const float* __restrict__ wfu, float* __restrict__ out, int N)
{
    extern __shared__ float sm[];
    float* sy0  = sm;           // 400
    float* sa   = sm + 400;     // 3200
    float* sb   = sa + 3200;    // 3200
    float* sy1  = sb + 3200;    // 3200
    float* ste  = sy1 + 3200;   // 144
    float* semb = ste + 144;    // 64

    int n = blockIdx.x;
    if (n >= N) return;
    int tid = threadIdx.x;
    int w = tid >> 5, lane = tid & 31;
    int lane2 = lane * 2;
    int lane4 = lane * 4;

    // ---- P1: loads ----
    for (int t = tid; t < 400; t += 256) sy0[t] = g_Y0[(size_t)n*400 + t];
    if (tid < 64) {
        int Z = __ldg(an + n);
        semb[tid] = __ldg(emb + (size_t)Z*64 + tid);
    }
    __syncthreads();

    // ---- P2: dd0 + te ----
    for (int it = c_dd0Start[w]; it < c_dd0Start[w+1]; it++) {
        unsigned I = c_dd0Item[it];
        int L = I & 7, q0 = (I>>4)&15, qn = (I>>8)&15;
        int lm0 = L*L + q0;
        dd_block<16>(sy0 + lm0*16,
                     sa + lm0*128 + lane4, sb + lm0*128 + lane4,
                     t0W1 + L*1024 + lane2, t0W2 + L*1024 + lane2,
                     qn, 16);
    }
    if (tid < 144) {
        float acc = __ldg(b_et + tid);
        #pragma unroll 8
        for (int d = 0; d < 64; d++)
            acc = fmaf(semb[d], __ldg(W_et + d*144 + tid), acc);
        ste[tid] = acc;
    }
    __syncthreads();

    // ---- P3: tp0 (parity0 only; register acc per ic; plain STS flush) ----
    {
        int g0 = c_sliceStart[w], g1 = c_sliceStart[w+1];
        const float* Abase = sa + lane4;
        const float* Bbase = sb + lane4;
        float p0x = 0.f, p0y = 0.f, p1x = 0.f, p1y = 0.f;
        for (int gi = g0; gi < g1; gi++) {
            uint2 G = __ldg(&g_grp[gi]);
            int start = G.x & 0xFFFF, cnt = (int)(G.x >> 16);
            int ic = G.y & 31, s = (G.y>>5)&1, fl = (G.y>>6)&1, path = (int)(G.y>>8);
            ull s00 = 0, a0 = 0;
            for (int k = 0; k < cnt; k++) {
                uint2 Ee = __ldg(&g_ent[start+k]);
                unsigned xi = Ee.x;
                if (xi & 0x8000u)
                    a0 = ld2s(Abase + (xi & 0x7FFFu));
                ull b0 = ld2s(Bbase + (xi >> 16));
                ull vv; SPLAT2(vv, Ee.y);
                ull p00; MUL2(p00, a0, b0);
                FMA2(s00, vv, p00, s00);
            }
            float2 t00 = unp(s00);
            float2 w00 = *(const float2*)(t0wp + path*256 + lane2);
            float ex = w00.x * t00.x, ey = w00.y * t00.y;
            if (s == 0) { p0x += ex; p0y += ey; }
            else        { p1x += ex; p1y += ey; }
            if (fl) {
                *(float2*)(sy1 + ic*128 + lane2)      = make_float2(p0x, p0y);
                *(float2*)(sy1 + ic*128 + 64 + lane2) = make_float2(p1x, p1y);
                p0x = p0y = p1x = p1y = 0.f;
            }
        }
    }
    __syncthreads();

    // ---- P4: dd1 ----
    for (int it = c_dd1Start[w]; it < c_dd1Start[w+1]; it++) {
        unsigned I = c_dd1Item[it];
        int L = I & 7, p = (I>>3)&1, q0 = (I>>4)&15, qn = (I>>8)&15;
        int lm0 = L*L + q0;
        dd_block<128>(sy1 + lm0*128 + p*64,
                      sa + lm0*128 + lane4 + 2*p, sb + lm0*128 + lane4 + 2*p,
                      t1W1 + p*20480 + L*4096 + lane2,
                      t1W2 + p*20480 + L*4096 + lane2,
                      qn, 64);
    }
    __syncthreads();

    // ---- P5: tp1 — flush applies epilogue + mish, STGs directly to out ----
    {
        int g0 = c_sliceStart[w], g1 = c_sliceStart[w+1];
        const float* Abase = sa + lane4;
        const float* Bbase = sb + lane4;
        float p0x = 0.f, p0y = 0.f, p1x = 0.f, p1y = 0.f;
        float2 stc = *(const float2*)(ste + 80 + lane2);
        for (int gi = g0; gi < g1; gi++) {
            uint2 G = __ldg(&g_grp[gi]);
            int start = G.x & 0xFFFF, cnt = (int)(G.x >> 16);
            int ic = G.y & 31, s = (G.y>>5)&1, fl = (G.y>>6)&1, path = (int)(G.y>>8);
            ull s00 = 0, s11 = 0, s01 = 0, s10 = 0;
            ull a0 = 0, a1 = 0;
            for (int k = 0; k < cnt; k++) {
                uint2 Ee = __ldg(&g_ent[start+k]);
                unsigned xi = Ee.x;
                if (xi & 0x8000u) {
                    ulonglong2 av = *(const ulonglong2*)(Abase + (xi & 0x7FFFu));
                    a0 = av.x; a1 = av.y;
                }
                ulonglong2 bv = *(const ulonglong2*)(Bbase + (xi >> 16));
                ull b0 = bv.x, b1 = bv.y;
                ull vv; SPLAT2(vv, Ee.y);
                ull p00, p11, p01, p10;
                MUL2(p00, a0, b0); MUL2(p11, a1, b1);
                MUL2(p01, a0, b1); MUL2(p10, a1, b0);
                FMA2(s00, vv, p00, s00);
                FMA2(s11, vv, p11, s11);
                FMA2(s01, vv, p01, s01);
                FMA2(s10, vv, p10, s10);
            }
            const float4* wp4 = (const float4*)(g_wpPack + path*256 + lane*8);
            float4 wA = __ldg(wp4);
            float4 wB = __ldg(wp4 + 1);
            float2 t00 = unp(s00), t11 = unp(s11), t01 = unp(s01), t10 = unp(s10);
            float evx = fmaf(wA.x, t00.x, wB.z * t11.x);
            float evy = fmaf(wA.y, t00.y, wB.w * t11.y);
            float odx = fmaf(wA.z, t01.x, wB.x * t10.x);
            float ody = fmaf(wA.w, t01.y, wB.y * t10.y);
            if (s == 0) { p0x += evx; p0y += evy; p1x += odx; p1y += ody; }
            else        { p0x += odx; p0y += ody; p1x += evx; p1y += evy; }
            if (fl) {
                int dg = ic>=16?4: ic>=9?3: ic>=4?2: ic>=1?1:0;
                float2 wf0 = *(const float2*)(wfu + dg*144 + 80 + lane2);
                float2 wf1 = *(const float2*)(wfu + 720 + dg*144 + 80 + lane2);
                float v0x = stc.x * p0x * wf0.x;
                float v0y = stc.y * p0y * wf0.y;
                float v1x = stc.x * p1x * wf1.x;
                float v1y = stc.y * p1y * wf1.y;
                if (ic == 0) { v0x += stc.x; v0y += stc.y; }
                size_t ob = (size_t)n*7200 + ic*144 + 80 + lane2;
                *(float2*)(out + ob)        = make_float2(mish(v0x), mish(v0y));
                *(float2*)(out + ob + 3600) = make_float2(mish(v1x), mish(v1y));
                p0x = p0y = p1x = p1y = 0.f;
            }
        }
    }
    __syncthreads();

    // ---- P6: epilogue for c<80 (sy0 + sy1 features) ----
    for (int t = tid; t < 4000; t += 256) {
        int p = t/2000, rem = t - p*2000;
        int lm = rem/80, c = rem - lm*80;
        float feat;
        if (c < 16) feat = p ? 0.f : sy0[lm*16 + c];
        else        feat = sy1[lm*128 + p*64 + (c-16)];
        int dg = lm>=16?4: lm>=9?3: lm>=4?2: lm>=1?1:0;
        float v = ste[c] * feat * __ldg(wfu + p*720 + dg*144 + c);
        if (p==0 && lm==0) v += ste[c];
        out[(size_t)n*7200 + p*3600 + lm*144 + c] = mish(v);
    }
}

// ------------------------- launch ------------------------------------------
extern "C" void kernel_launch(void* const* d_in, const int* in_sizes, int n_in,
                              void* d_out, int out_size)
{
    tab::build();

    const int*   an   = (const int*)d_in[0];
    const int*   nbr  = (const int*)d_in[1];
    const float* disp = (const float*)d_in[2];
    const float* Wsp  = (const float*)d_in[3];
    const float* emb  = (const float*)d_in[4];
    const float* W_et = (const float*)d_in[5];
    const float* b_et = (const float*)d_in[6];
    const float* norm = (const float*)d_in[7];
    const float* t0W1 = (const float*)d_in[8];
    const float* t0W2 = (const float*)d_in[9];
    const float* t0wp = (const float*)d_in[10];
    const float* t1W1 = (const float*)d_in[11];
    const float* t1W2 = (const float*)d_in[12];
    const float* t1wp = (const float*)d_in[13];
    const float* wfu  = (const float*)d_in[14];
    float* out = (float*)d_out;

    int N = in_sizes[0];
    int E = in_sizes[1] / 2;

    cudaMemcpyToSymbolAsync(g_ent, tab::h_ent, tab::nent*sizeof(uint2),
                            0, cudaMemcpyHostToDevice, 0);
    cudaMemcpyToSymbolAsync(g_grp, tab::h_grp, tab::ngrp*sizeof(uint2),
                            0, cudaMemcpyHostToDevice, 0);
    cudaMemcpyToSymbolAsync(c_sliceStart, tab::h_sliceStart, (NSLICE+1)*sizeof(int),
                            0, cudaMemcpyHostToDevice, 0);
    cudaMemcpyToSymbolAsync(c_dd0Start, tab::h_dd0Start, (NSLICE+1)*sizeof(int),
                            0, cudaMemcpyHostToDevice, 0);
    cudaMemcpyToSymbolAsync(c_dd1Start, tab::h_dd1Start, (NSLICE+1)*sizeof(int),
                            0, cudaMemcpyHostToDevice, 0);
    cudaMemcpyToSymbolAsync(c_dd0Item, tab::h_dd0Item, sizeof(tab::h_dd0Item),
                            0, cudaMemcpyHostToDevice, 0);
    cudaMemcpyToSymbolAsync(c_dd1Item, tab::h_dd1Item, sizeof(tab::h_dd1Item),
                            0, cudaMemcpyHostToDevice, 0);

    void* y0ptr = nullptr;
    cudaGetSymbolAddress(&y0ptr, g_Y0);
    cudaMemsetAsync(y0ptr, 0, (size_t)N*400*sizeof(float), 0);

    repack_wp<<<65, 256>>>(t1wp);
    edge_kernel<<<(E + 7)/8, 256>>>(an, nbr, disp, Wsp, norm, E);

    static bool attr_done = false;
    size_t smem = 10208 * sizeof(float);
    if (!attr_done) {
        cudaFuncSetAttribute(atom_kernel, cudaFuncAttributeMaxDynamicSharedMemorySize,
                             (int)smem);
        attr_done = true;
    }
    atom_kernel<<<N, 256, smem>>>(an, emb, W_et, b_et, t0W1, t0W2, t0wp,
                                  t1W1, t1W2, wfu, out, N);
}